// round 10
// baseline (speedup 1.0000x reference)
#include <cuda_runtime.h>
#include <cuda_fp16.h>
#include <cstdint>

// Problem constants
#define BATCH 2
#define SEQ   2048
#define DIM   1024
#define HEADS 16
#define HD    64
#define NTOK  (BATCH*SEQ)   // 4096

// ---------------------------------------------------------------------------
// Scratch (__device__ globals; allocation-free rule)
// ---------------------------------------------------------------------------
__device__ __half g_xhi[(size_t)NTOK * DIM];
__device__ __half g_xlo[(size_t)NTOK * DIM];
__device__ __half g_wqh[(size_t)3 * DIM * DIM];     // weights: hi only
__device__ __half g_woh[(size_t)DIM * DIM];
__device__ __half g_qhi[(size_t)NTOK * DIM];        // Q (pre-scaled) hi
__device__ __half g_qlo[(size_t)NTOK * DIM];        // Q lo
__device__ __half g_khi[(size_t)NTOK * DIM];        // K hi
__device__ __half g_vhi[(size_t)NTOK * DIM];        // V hi
__device__ __half g_ahi[(size_t)NTOK * DIM];        // attn out hi
__device__ __half g_alo[(size_t)NTOK * DIM];        // attn out lo

// ---------------------------------------------------------------------------
// PTX helpers (baseline sm_100-safe)
// ---------------------------------------------------------------------------
__device__ __forceinline__ uint32_t smem_u32(const void* p) {
    uint32_t a;
    asm("{ .reg .u64 t; cvta.to.shared.u64 t, %1; cvt.u32.u64 %0, t; }" : "=r"(a) : "l"(p));
    return a;
}
#define SWZ64(off)  ((off) ^ (((off) >> 3) & 0x30))
#define SWZ128(off) ((off) ^ (((off) >> 3) & 0x70))

#define CP_ASYNC16(saddr, gptr) \
    asm volatile("cp.async.cg.shared.global [%0], [%1], 16;\n" :: "r"(saddr), "l"(gptr))
#define CP_COMMIT() asm volatile("cp.async.commit_group;\n" ::: "memory")
#define CP_WAIT(N)  asm volatile("cp.async.wait_group %0;\n" :: "n"(N) : "memory")

#define LDSM_X4(r0, r1, r2, r3, addr) \
    asm volatile("ldmatrix.sync.aligned.m8n8.x4.shared.b16 {%0,%1,%2,%3}, [%4];" \
                 : "=r"(r0), "=r"(r1), "=r"(r2), "=r"(r3) : "r"(addr))
#define LDSM_X4_T(r0, r1, r2, r3, addr) \
    asm volatile("ldmatrix.sync.aligned.m8n8.x4.trans.shared.b16 {%0,%1,%2,%3}, [%4];" \
                 : "=r"(r0), "=r"(r1), "=r"(r2), "=r"(r3) : "r"(addr))

#define MMAF16(c, a, b0, b1) \
    asm volatile("mma.sync.aligned.m16n8k16.row.col.f32.f16.f16.f32 " \
                 "{%0,%1,%2,%3}, {%4,%5,%6,%7}, {%8,%9}, {%0,%1,%2,%3};" \
                 : "+f"((c)[0]), "+f"((c)[1]), "+f"((c)[2]), "+f"((c)[3]) \
                 : "r"((a)[0]), "r"((a)[1]), "r"((a)[2]), "r"((a)[3]), \
                   "r"(b0), "r"(b1))

__device__ __forceinline__ uint32_t pack_h2(float a, float b) {
    __half2 v(__float2half(a), __float2half(b));
    return *(uint32_t*)&v;
}

// ---------------------------------------------------------------------------
// fused split kernel: x -> hi/lo; weights -> hi only
// ---------------------------------------------------------------------------
#define N4_X  (NTOK * DIM / 4)
#define N4_WQ (3 * DIM * DIM / 4)
#define N4_WO (DIM * DIM / 4)

__global__ void split_all(const float* __restrict__ x,  __half* __restrict__ xhi, __half* __restrict__ xlo,
                          const float* __restrict__ wq, __half* __restrict__ wqh,
                          const float* __restrict__ wo, __half* __restrict__ woh)
{
    int i = blockIdx.x * blockDim.x + threadIdx.x;
    if (i < N4_X) {
        float4 v = ((const float4*)x)[i];
        __half h0 = __float2half(v.x), h1 = __float2half(v.y);
        __half h2 = __float2half(v.z), h3 = __float2half(v.w);
        __half2* hp = (__half2*)(xhi + (size_t)i * 4);
        __half2* lp = (__half2*)(xlo + (size_t)i * 4);
        hp[0] = __half2(h0, h1);
        hp[1] = __half2(h2, h3);
        lp[0] = __half2(__float2half(v.x - __half2float(h0)),
                        __float2half(v.y - __half2float(h1)));
        lp[1] = __half2(__float2half(v.z - __half2float(h2)),
                        __float2half(v.w - __half2float(h3)));
        return;
    }
    int j = i - N4_X;
    const float* src; __half* dst;
    if (j < N4_WQ) { src = wq; dst = wqh; }
    else if (j < N4_WQ + N4_WO) { j -= N4_WQ; src = wo; dst = woh; }
    else return;
    float4 v = ((const float4*)src)[j];
    __half2* hp = (__half2*)(dst + (size_t)j * 4);
    hp[0] = __half2(__float2half(v.x), __float2half(v.y));
    hp[1] = __half2(__float2half(v.z), __float2half(v.w));
}

// ---------------------------------------------------------------------------
// 2-term fp16 GEMM mainloop (shared by both GEMM kernels via macro body)
// CTA tile 128x128, 128 threads (4 warps x 64x64), BK=32, 3 stages.
// ---------------------------------------------------------------------------
#define BM 128
#define BN 128
#define BK 32
#define NSTAGE 3
#define A_BYTES (BM * BK * 2)              // 8192 per term
#define B_BYTES (BN * BK * 2)              // 8192 (hi only)
#define STAGE_B (2*A_BYTES + B_BYTES)      // 24576
#define GEMM_SMEM (NSTAGE * STAGE_B)       // 73728

// Shared mainloop: leaves accumulators in c[4][8][4]
#define GEMM_MAINLOOP(Ahi, Alo, Bh, K)                                              \
    extern __shared__ __align__(1024) char smem[];                                  \
    const uint32_t sbase = smem_u32(smem);                                          \
    const int tid  = threadIdx.x;                                                   \
    const int wid  = tid >> 5;                                                      \
    const int lane = tid & 31;                                                      \
    const int m0 = blockIdx.y * BM;                                                 \
    const int n0 = blockIdx.x * BN;                                                 \
    const int m_off = (wid & 1) * 64;                                               \
    const int n_off = (wid >> 1) * 64;                                              \
    const __half* aS[2] = { Ahi + (size_t)m0 * K, Alo + (size_t)m0 * K };           \
    const __half* bSrc  = Bh + (size_t)n0 * K;                                      \
    const int NIT = K / BK;                                                         \
    auto load_stage = [&](int sbuf, int k0) {                                       \
        uint32_t stg = sbase + sbuf * STAGE_B;                                      \
        _Pragma("unroll")                                                           \
        for (int p = 0; p < 2; p++) {                                               \
            uint32_t part = stg + p * A_BYTES;                                      \
            const __half* src = aS[p] + k0;                                         \
            _Pragma("unroll")                                                       \
            for (int r = 0; r < 4; r++) {                                           \
                int idx = r * 128 + tid;                                            \
                int row = idx >> 2, cch = idx & 3;                                  \
                uint32_t soff = SWZ64((uint32_t)(row * 64 + cch * 16));             \
                CP_ASYNC16(part + soff, src + (size_t)row * K + cch * 8);           \
            }                                                                       \
        }                                                                           \
        {                                                                           \
            uint32_t part = stg + 2 * A_BYTES;                                      \
            const __half* src = bSrc + k0;                                          \
            _Pragma("unroll")                                                       \
            for (int r = 0; r < 4; r++) {                                           \
                int idx = r * 128 + tid;                                            \
                int row = idx >> 2, cch = idx & 3;                                  \
                uint32_t soff = SWZ64((uint32_t)(row * 64 + cch * 16));             \
                CP_ASYNC16(part + soff, src + (size_t)row * K + cch * 8);           \
            }                                                                       \
        }                                                                           \
    };                                                                              \
    float c[4][8][4];                                                               \
    _Pragma("unroll")                                                               \
    for (int i = 0; i < 4; i++)                                                     \
        _Pragma("unroll")                                                           \
        for (int j = 0; j < 8; j++)                                                 \
            _Pragma("unroll")                                                       \
            for (int t = 0; t < 4; t++) c[i][j][t] = 0.f;                           \
    load_stage(0, 0); CP_COMMIT();                                                  \
    load_stage(1, BK); CP_COMMIT();                                                 \
    const int lr = lane & 15;                                                       \
    const int lk = lane >> 4;                                                       \
    int sbuf = 0;                                                                   \
    for (int it = 0; it < NIT; it++) {                                              \
        CP_WAIT(1);                                                                 \
        __syncthreads();                                                            \
        if (it + 2 < NIT) { load_stage((sbuf + 2) % 3, (it + 2) * BK); CP_COMMIT(); } \
        uint32_t stg  = sbase + sbuf * STAGE_B;                                     \
        uint32_t aHiB = stg;                                                        \
        uint32_t aLoB = stg + A_BYTES;                                              \
        uint32_t bHiB = stg + 2 * A_BYTES;                                          \
        _Pragma("unroll")                                                           \
        for (int ks = 0; ks < 2; ks++) {                                            \
            uint32_t ahi[4][4], alo[4][4];                                          \
            _Pragma("unroll")                                                       \
            for (int mi = 0; mi < 4; mi++) {                                        \
                uint32_t sw = SWZ64((uint32_t)((m_off + mi * 16 + lr) * 64 + ks * 32 + lk * 16)); \
                LDSM_X4(ahi[mi][0], ahi[mi][1], ahi[mi][2], ahi[mi][3], aHiB + sw); \
                LDSM_X4(alo[mi][0], alo[mi][1], alo[mi][2], alo[mi][3], aLoB + sw); \
            }                                                                       \
            _Pragma("unroll")                                                       \
            for (int ng = 0; ng < 4; ng++) {                                        \
                uint32_t sw = SWZ64((uint32_t)((n_off + ng * 16 + lr) * 64 + ks * 32 + lk * 16)); \
                uint32_t bh0, bh1, bh2, bh3;                                        \
                LDSM_X4(bh0, bh1, bh2, bh3, bHiB + sw);                             \
                _Pragma("unroll")                                                   \
                for (int mi = 0; mi < 4; mi++) {                                    \
                    MMAF16(c[mi][ng*2+0], ahi[mi], bh0, bh2);                       \
                    MMAF16(c[mi][ng*2+1], ahi[mi], bh1, bh3);                       \
                    MMAF16(c[mi][ng*2+0], alo[mi], bh0, bh2);                       \
                    MMAF16(c[mi][ng*2+1], alo[mi], bh1, bh3);                       \
                }                                                                   \
            }                                                                       \
        }                                                                           \
        sbuf = (sbuf + 1) % 3;                                                      \
    }                                                                               \
    const int cr = lane >> 2;                                                       \
    const int cc = (lane & 3) * 2;

// ---------------------------------------------------------------------------
// GEMM1: qkv projection, epilogue writes Q(hi/lo, pre-scaled), K(hi), V(hi)
// N = 3072; each 128-col tile lies wholly in Q, K, or V.
// ---------------------------------------------------------------------------
__global__ __launch_bounds__(128, 2)
void gemm_qkv(const __half* __restrict__ Ahi, const __half* __restrict__ Alo,
              const __half* __restrict__ Bh,
              __half* __restrict__ qhi, __half* __restrict__ qlo,
              __half* __restrict__ khi, __half* __restrict__ vhi)
{
    GEMM_MAINLOOP(Ahi, Alo, Bh, DIM)

    const int seg  = n0 >> 10;           // 0=Q, 1=K, 2=V
    const int col0 = (n0 & 1023) + n_off;
#pragma unroll
    for (int mi = 0; mi < 4; mi++) {
        int r0 = m0 + m_off + mi * 16 + cr;
#pragma unroll
        for (int j = 0; j < 8; j++) {
            int col = col0 + j * 8 + cc;
#pragma unroll
            for (int half = 0; half < 2; half++) {
                int row = r0 + half * 8;
                float v0 = c[mi][j][half * 2 + 0];
                float v1 = c[mi][j][half * 2 + 1];
                size_t off = (size_t)row * DIM + col;
                if (seg == 0) {
                    v0 *= 0.125f; v1 *= 0.125f;
                    __half h0 = __float2half(v0), h1 = __float2half(v1);
                    *(uint32_t*)(qhi + off) = pack_h2(v0, v1);
                    *(uint32_t*)(qlo + off) =
                        pack_h2(v0 - __half2float(h0), v1 - __half2float(h1));
                } else if (seg == 1) {
                    *(uint32_t*)(khi + off) = pack_h2(v0, v1);
                } else {
                    *(uint32_t*)(vhi + off) = pack_h2(v0, v1);
                }
            }
        }
    }
}

// ---------------------------------------------------------------------------
// GEMM2: out projection (fp32 out)
// ---------------------------------------------------------------------------
__global__ __launch_bounds__(128, 2)
void gemm_out(const __half* __restrict__ Ahi, const __half* __restrict__ Alo,
              const __half* __restrict__ Bh, float* __restrict__ C)
{
    GEMM_MAINLOOP(Ahi, Alo, Bh, DIM)

#pragma unroll
    for (int mi = 0; mi < 4; mi++) {
        int r0 = m0 + m_off + mi * 16 + cr;
#pragma unroll
        for (int j = 0; j < 8; j++) {
            int col = n0 + n_off + j * 8 + cc;
            *(float2*)(C + (size_t)r0 * DIM + col)       = make_float2(c[mi][j][0], c[mi][j][1]);
            *(float2*)(C + (size_t)(r0 + 8) * DIM + col) = make_float2(c[mi][j][2], c[mi][j][3]);
        }
    }
}

// ---------------------------------------------------------------------------
// Tensor-core flash attention (2-term fp16): ALiBi + causal.
// Inputs already fp16: Q hi/lo (pre-scaled), K hi, V hi.
// cp.async double-buffered K/V tiles; 2 CTAs/SM.
// ---------------------------------------------------------------------------
// smem: Q_HI 0 (16384), Q_LO 16384, stages at 32768 (Khi 8192 + Vhi 8192) x2,
//       P_HI 65536, P_LO 81920 -> total 98304
#define ATT_SMEM 98304
#define Q_HI 0
#define Q_LO 16384
#define STG0 32768
#define P_HI 65536
#define P_LO 81920

__global__ __launch_bounds__(256, 2)
void attn_mma(const __half* __restrict__ qhi, const __half* __restrict__ qlo,
              const __half* __restrict__ khi, const __half* __restrict__ vhi,
              __half* __restrict__ out_hi, __half* __restrict__ out_lo)
{
    extern __shared__ __align__(1024) char smem[];
    const uint32_t sbase = smem_u32(smem);
    const int tid  = threadIdx.x;
    const int wid  = tid >> 5;
    const int lane = tid & 31;
    const int lr   = lane & 15;
    const int lk   = lane >> 4;

    const int qt = (int)(gridDim.x - 1 - blockIdx.x);   // largest tiles first
    const int bh = blockIdx.y;
    const int b  = bh >> 4;
    const int h  = bh & 15;
    const int q0 = qt * 128;

    const float slope = exp2f(-0.5f * (float)(h + 1));

    const __half* qh_base = qhi + (size_t)(b * SEQ) * DIM + h * HD;
    const __half* ql_base = qlo + (size_t)(b * SEQ) * DIM + h * HD;
    const __half* kh_base = khi + (size_t)(b * SEQ) * DIM + h * HD;
    const __half* vh_base = vhi + (size_t)(b * SEQ) * DIM + h * HD;

    // ---- issue Q tile loads (128 rows x 128 B, hi + lo) ----
#pragma unroll
    for (int r = 0; r < 4; r++) {
        int idx = r * 256 + tid;          // 0..1023
        int row = idx >> 3;
        int ch  = idx & 7;
        uint32_t soff = SWZ128((uint32_t)(row * 128 + ch * 16));
        CP_ASYNC16(sbase + Q_HI + soff, qh_base + (size_t)(q0 + row) * DIM + ch * 8);
        CP_ASYNC16(sbase + Q_LO + soff, ql_base + (size_t)(q0 + row) * DIM + ch * 8);
    }

    const int nkt = 2 * qt + 2;

    // issue K/V tile kt into stage s
    auto issue_kv = [&](int kt, int s) {
        uint32_t stg = sbase + STG0 + s * 16384;
        int k0 = kt * 64;
#pragma unroll
        for (int r = 0; r < 2; r++) {
            int idx = r * 256 + tid;      // 0..511
            int row = idx >> 3;
            int ch  = idx & 7;
            uint32_t soff = SWZ128((uint32_t)(row * 128 + ch * 16));
            CP_ASYNC16(stg + soff,        kh_base + (size_t)(k0 + row) * DIM + ch * 8);
            CP_ASYNC16(stg + 8192 + soff, vh_base + (size_t)(k0 + row) * DIM + ch * 8);
        }
    };

    issue_kv(0, 0);
    CP_COMMIT();                           // group: Q + KV0

    float cs[8][4];
    float co[8][4];
#pragma unroll
    for (int j = 0; j < 8; j++)
#pragma unroll
        for (int t = 0; t < 4; t++) co[j][t] = 0.f;

    float m0v = -1e30f, m1v = -1e30f, l0v = 0.f, l1v = 0.f;

    const int r0 = lane >> 2;
    const int ccol = (lane & 3) * 2;
    const int gi0 = q0 + wid * 16 + r0;
    const int gi1 = gi0 + 8;

    for (int kt = 0; kt < nkt; kt++) {
        const int s = kt & 1;
        const int k0 = kt * 64;
        const uint32_t stgo = STG0 + s * 16384;

        __syncthreads();                   // prior reads of stage s^1 done
        if (kt + 1 < nkt) {
            issue_kv(kt + 1, s ^ 1);
            CP_COMMIT();
            CP_WAIT(1);
        } else {
            CP_WAIT(0);
        }
        __syncthreads();                   // stage s (and Q on kt=0) visible

        // ---- S = Q K^T (2-term) ----
#pragma unroll
        for (int j = 0; j < 8; j++)
#pragma unroll
            for (int t = 0; t < 4; t++) cs[j][t] = 0.f;

        uint32_t kHiB = sbase + stgo;
#pragma unroll
        for (int ks = 0; ks < 4; ks++) {
            uint32_t qoff = SWZ128((uint32_t)((wid * 16 + lr) * 128 + ks * 32 + lk * 16));
            uint32_t ahi[4], alo[4];
            LDSM_X4(ahi[0], ahi[1], ahi[2], ahi[3], sbase + Q_HI + qoff);
            LDSM_X4(alo[0], alo[1], alo[2], alo[3], sbase + Q_LO + qoff);
#pragma unroll
            for (int ng = 0; ng < 4; ng++) {
                uint32_t boff = SWZ128((uint32_t)((ng * 16 + lr) * 128 + ks * 32 + lk * 16));
                uint32_t bh0, bh1, bh2, bh3;
                LDSM_X4(bh0, bh1, bh2, bh3, kHiB + boff);
                MMAF16(cs[ng*2+0], ahi, bh0, bh2);
                MMAF16(cs[ng*2+1], ahi, bh1, bh3);
                MMAF16(cs[ng*2+0], alo, bh0, bh2);
                MMAF16(cs[ng*2+1], alo, bh1, bh3);
            }
        }

        // ---- ALiBi + causal mask ----
#pragma unroll
        for (int nb = 0; nb < 8; nb++) {
#pragma unroll
            for (int cidx = 0; cidx < 2; cidx++) {
                int gj = k0 + nb * 8 + ccol + cidx;
                float rel0 = slope * (float)(gj - gi0);
                float rel1 = slope * (float)(gj - gi1);
                cs[nb][cidx]     = (gj > gi0) ? -1e30f : cs[nb][cidx]     - rel0;
                cs[nb][2 + cidx] = (gj > gi1) ? -1e30f : cs[nb][2 + cidx] - rel1;
            }
        }

        // ---- online softmax ----
        float mx0 = -1e30f, mx1 = -1e30f;
#pragma unroll
        for (int nb = 0; nb < 8; nb++) {
            mx0 = fmaxf(mx0, fmaxf(cs[nb][0], cs[nb][1]));
            mx1 = fmaxf(mx1, fmaxf(cs[nb][2], cs[nb][3]));
        }
        mx0 = fmaxf(mx0, __shfl_xor_sync(0xffffffff, mx0, 1));
        mx0 = fmaxf(mx0, __shfl_xor_sync(0xffffffff, mx0, 2));
        mx1 = fmaxf(mx1, __shfl_xor_sync(0xffffffff, mx1, 1));
        mx1 = fmaxf(mx1, __shfl_xor_sync(0xffffffff, mx1, 2));

        float mn0 = fmaxf(m0v, mx0), mn1 = fmaxf(m1v, mx1);
        float corr0 = __expf(m0v - mn0), corr1 = __expf(m1v - mn1);
        m0v = mn0; m1v = mn1;

        float sum0 = 0.f, sum1 = 0.f;
        const int prow0 = wid * 16 + r0;
#pragma unroll
        for (int nb = 0; nb < 8; nb++) {
            float p00 = __expf(cs[nb][0] - mn0);
            float p01 = __expf(cs[nb][1] - mn0);
            float p10 = __expf(cs[nb][2] - mn1);
            float p11 = __expf(cs[nb][3] - mn1);
            sum0 += p00 + p01;
            sum1 += p10 + p11;
            uint32_t off0 = SWZ128((uint32_t)(prow0 * 128 + nb * 16 + (lane & 3) * 4));
            uint32_t off1 = SWZ128((uint32_t)((prow0 + 8) * 128 + nb * 16 + (lane & 3) * 4));
            __half h00 = __float2half(p00), h01 = __float2half(p01);
            __half h10 = __float2half(p10), h11 = __float2half(p11);
            *(uint32_t*)(smem + P_HI + off0) = pack_h2(p00, p01);
            *(uint32_t*)(smem + P_HI + off1) = pack_h2(p10, p11);
            *(uint32_t*)(smem + P_LO + off0) =
                pack_h2(p00 - __half2float(h00), p01 - __half2float(h01));
            *(uint32_t*)(smem + P_LO + off1) =
                pack_h2(p10 - __half2float(h10), p11 - __half2float(h11));
        }
        sum0 += __shfl_xor_sync(0xffffffff, sum0, 1);
        sum0 += __shfl_xor_sync(0xffffffff, sum0, 2);
        sum1 += __shfl_xor_sync(0xffffffff, sum1, 1);
        sum1 += __shfl_xor_sync(0xffffffff, sum1, 2);
        l0v = l0v * corr0 + sum0;
        l1v = l1v * corr1 + sum1;

#pragma unroll
        for (int nb = 0; nb < 8; nb++) {
            co[nb][0] *= corr0; co[nb][1] *= corr0;
            co[nb][2] *= corr1; co[nb][3] *= corr1;
        }
        __syncwarp();

        // ---- O += P V (2-term; V hi via ldmatrix.trans) ----
        uint32_t vHiB = sbase + stgo + 8192;
#pragma unroll
        for (int ks = 0; ks < 4; ks++) {
            uint32_t poff = SWZ128((uint32_t)((wid * 16 + lr) * 128 + ks * 32 + lk * 16));
            uint32_t phi[4], plo[4];
            LDSM_X4(phi[0], phi[1], phi[2], phi[3], sbase + P_HI + poff);
            LDSM_X4(plo[0], plo[1], plo[2], plo[3], sbase + P_LO + poff);
#pragma unroll
            for (int ng = 0; ng < 4; ng++) {
                uint32_t voff = SWZ128((uint32_t)((ks * 16 + lr) * 128 + ng * 32 + lk * 16));
                uint32_t vh0, vh1, vh2, vh3;
                LDSM_X4_T(vh0, vh1, vh2, vh3, vHiB + voff);
                MMAF16(co[ng*2+0], phi, vh0, vh1);
                MMAF16(co[ng*2+1], phi, vh2, vh3);
                MMAF16(co[ng*2+0], plo, vh0, vh1);
                MMAF16(co[ng*2+1], plo, vh2, vh3);
            }
        }
    }

    // ---- normalize + write fp16 hi/lo ----
    float inv0 = 1.0f / l0v, inv1 = 1.0f / l1v;
    size_t row0 = (size_t)(b * SEQ + gi0) * DIM + h * HD;
    size_t row1 = (size_t)(b * SEQ + gi1) * DIM + h * HD;
#pragma unroll
    for (int nb = 0; nb < 8; nb++) {
        int d = nb * 8 + ccol;
        float o00 = co[nb][0] * inv0, o01 = co[nb][1] * inv0;
        float o10 = co[nb][2] * inv1, o11 = co[nb][3] * inv1;
        __half h00 = __float2half(o00), h01 = __float2half(o01);
        __half h10 = __float2half(o10), h11 = __float2half(o11);
        *(uint32_t*)(out_hi + row0 + d) = pack_h2(o00, o01);
        *(uint32_t*)(out_hi + row1 + d) = pack_h2(o10, o11);
        *(uint32_t*)(out_lo + row0 + d) =
            pack_h2(o00 - __half2float(h00), o01 - __half2float(h01));
        *(uint32_t*)(out_lo + row1 + d) =
            pack_h2(o10 - __half2float(h10), o11 - __half2float(h11));
    }
}

// ---------------------------------------------------------------------------
extern "C" void kernel_launch(void* const* d_in, const int* in_sizes, int n_in,
                              void* d_out, int out_size)
{
    const float* x    = (const float*)d_in[0];
    const float* Wqkv = (const float*)d_in[1];
    const float* Wo   = (const float*)d_in[2];
    float* out = (float*)d_out;

    __half *xhi, *xlo, *wqh, *woh, *qhi, *qlo, *khi, *vhi, *ahi, *alo;
    cudaGetSymbolAddress((void**)&xhi, g_xhi);
    cudaGetSymbolAddress((void**)&xlo, g_xlo);
    cudaGetSymbolAddress((void**)&wqh, g_wqh);
    cudaGetSymbolAddress((void**)&woh, g_woh);
    cudaGetSymbolAddress((void**)&qhi, g_qhi);
    cudaGetSymbolAddress((void**)&qlo, g_qlo);
    cudaGetSymbolAddress((void**)&khi, g_khi);
    cudaGetSymbolAddress((void**)&vhi, g_vhi);
    cudaGetSymbolAddress((void**)&ahi, g_ahi);
    cudaGetSymbolAddress((void**)&alo, g_alo);

    cudaFuncSetAttribute(gemm_qkv, cudaFuncAttributeMaxDynamicSharedMemorySize, GEMM_SMEM);
    cudaFuncSetAttribute(gemm_out, cudaFuncAttributeMaxDynamicSharedMemorySize, GEMM_SMEM);
    cudaFuncSetAttribute(attn_mma, cudaFuncAttributeMaxDynamicSharedMemorySize, ATT_SMEM);

    // fused hi/lo splits (x) + hi conversions (weights)
    {
        int n4 = N4_X + N4_WQ + N4_WO;
        split_all<<<(n4 + 255) / 256, 256>>>(x, xhi, xlo, Wqkv, wqh, Wo, woh);
    }

    // 1) qkv projection -> fp16 Q(hi/lo, scaled), K(hi), V(hi)
    {
        dim3 grid(3 * DIM / BN, NTOK / BM);   // (24, 32)
        gemm_qkv<<<grid, 128, GEMM_SMEM>>>(xhi, xlo, wqh, qhi, qlo, khi, vhi);
    }

    // 2) tensor-core flash attention (fp16 in, fp16 hi/lo out)
    {
        dim3 grid(SEQ / 128, BATCH * HEADS);   // (16, 32)
        attn_mma<<<grid, 256, ATT_SMEM>>>(qhi, qlo, khi, vhi, ahi, alo);
    }

    // 3) out = attn @ Wo^T (fp32 out)
    {
        dim3 grid(DIM / BN, NTOK / BM);        // (8, 32)
        gemm_out<<<grid, 128, GEMM_SMEM>>>(ahi, alo, woh, out);
    }
}

// round 11
// speedup vs baseline: 1.1870x; 1.1870x over previous
#include <cuda_runtime.h>
#include <cuda_fp16.h>
#include <cstdint>

// Problem constants
#define BATCH 2
#define SEQ   2048
#define DIM   1024
#define HEADS 16
#define HD    64
#define NTOK  (BATCH*SEQ)   // 4096

// ---------------------------------------------------------------------------
// Scratch (__device__ globals; allocation-free rule)
// ---------------------------------------------------------------------------
__device__ __half g_xhi[(size_t)NTOK * DIM];
__device__ __half g_xlo[(size_t)NTOK * DIM];
__device__ __half g_wqh[(size_t)3 * DIM * DIM];     // weights: hi only
__device__ __half g_woh[(size_t)DIM * DIM];
__device__ __half g_qhi[(size_t)NTOK * DIM];        // Q (pre-scaled) hi
__device__ __half g_qlo[(size_t)NTOK * DIM];        // Q lo
__device__ __half g_khi[(size_t)NTOK * DIM];        // K hi
__device__ __half g_vhi[(size_t)NTOK * DIM];        // V hi
__device__ __half g_ahi[(size_t)NTOK * DIM];        // attn out hi

// ---------------------------------------------------------------------------
// PTX helpers (baseline sm_100-safe)
// ---------------------------------------------------------------------------
__device__ __forceinline__ uint32_t smem_u32(const void* p) {
    uint32_t a;
    asm("{ .reg .u64 t; cvta.to.shared.u64 t, %1; cvt.u32.u64 %0, t; }" : "=r"(a) : "l"(p));
    return a;
}
#define SWZ64(off)  ((off) ^ (((off) >> 3) & 0x30))
#define SWZ128(off) ((off) ^ (((off) >> 3) & 0x70))

#define CP_ASYNC16(saddr, gptr) \
    asm volatile("cp.async.cg.shared.global [%0], [%1], 16;\n" :: "r"(saddr), "l"(gptr))
#define CP_COMMIT() asm volatile("cp.async.commit_group;\n" ::: "memory")
#define CP_WAIT(N)  asm volatile("cp.async.wait_group %0;\n" :: "n"(N) : "memory")

#define LDSM_X4(r0, r1, r2, r3, addr) \
    asm volatile("ldmatrix.sync.aligned.m8n8.x4.shared.b16 {%0,%1,%2,%3}, [%4];" \
                 : "=r"(r0), "=r"(r1), "=r"(r2), "=r"(r3) : "r"(addr))
#define LDSM_X4_T(r0, r1, r2, r3, addr) \
    asm volatile("ldmatrix.sync.aligned.m8n8.x4.trans.shared.b16 {%0,%1,%2,%3}, [%4];" \
                 : "=r"(r0), "=r"(r1), "=r"(r2), "=r"(r3) : "r"(addr))

#define MMAF16(c, a, b0, b1) \
    asm volatile("mma.sync.aligned.m16n8k16.row.col.f32.f16.f16.f32 " \
                 "{%0,%1,%2,%3}, {%4,%5,%6,%7}, {%8,%9}, {%0,%1,%2,%3};" \
                 : "+f"((c)[0]), "+f"((c)[1]), "+f"((c)[2]), "+f"((c)[3]) \
                 : "r"((a)[0]), "r"((a)[1]), "r"((a)[2]), "r"((a)[3]), \
                   "r"(b0), "r"(b1))

__device__ __forceinline__ uint32_t pack_h2(float a, float b) {
    __half2 v(__float2half(a), __float2half(b));
    return *(uint32_t*)&v;
}

// ---------------------------------------------------------------------------
// fused split kernel: x -> hi/lo; weights -> hi only
// ---------------------------------------------------------------------------
#define N4_X  (NTOK * DIM / 4)
#define N4_WQ (3 * DIM * DIM / 4)
#define N4_WO (DIM * DIM / 4)

__global__ void split_all(const float* __restrict__ x,  __half* __restrict__ xhi, __half* __restrict__ xlo,
                          const float* __restrict__ wq, __half* __restrict__ wqh,
                          const float* __restrict__ wo, __half* __restrict__ woh)
{
    int i = blockIdx.x * blockDim.x + threadIdx.x;
    if (i < N4_X) {
        float4 v = ((const float4*)x)[i];
        __half h0 = __float2half(v.x), h1 = __float2half(v.y);
        __half h2 = __float2half(v.z), h3 = __float2half(v.w);
        __half2* hp = (__half2*)(xhi + (size_t)i * 4);
        __half2* lp = (__half2*)(xlo + (size_t)i * 4);
        hp[0] = __half2(h0, h1);
        hp[1] = __half2(h2, h3);
        lp[0] = __half2(__float2half(v.x - __half2float(h0)),
                        __float2half(v.y - __half2float(h1)));
        lp[1] = __half2(__float2half(v.z - __half2float(h2)),
                        __float2half(v.w - __half2float(h3)));
        return;
    }
    int j = i - N4_X;
    const float* src; __half* dst;
    if (j < N4_WQ) { src = wq; dst = wqh; }
    else if (j < N4_WQ + N4_WO) { j -= N4_WQ; src = wo; dst = woh; }
    else return;
    float4 v = ((const float4*)src)[j];
    __half2* hp = (__half2*)(dst + (size_t)j * 4);
    hp[0] = __half2(__float2half(v.x), __float2half(v.y));
    hp[1] = __half2(__float2half(v.z), __float2half(v.w));
}

// ---------------------------------------------------------------------------
// GEMM common tile constants
// ---------------------------------------------------------------------------
#define BM 128
#define BN 128
#define BK 32
#define A_BYTES (BM * BK * 2)              // 8192 per term
#define B_BYTES (BN * BK * 2)              // 8192 (hi only)

// ---- 2-term mainloop (A hi+lo, B hi) -> c[4][8][4] ----
#define STAGE2_B (2*A_BYTES + B_BYTES)     // 24576
#define GEMM2T_SMEM (3 * STAGE2_B)         // 73728

#define GEMM_MAINLOOP_2T(Ahi, Alo, Bh, K)                                           \
    extern __shared__ __align__(1024) char smem[];                                  \
    const uint32_t sbase = smem_u32(smem);                                          \
    const int tid  = threadIdx.x;                                                   \
    const int wid  = tid >> 5;                                                      \
    const int lane = tid & 31;                                                      \
    const int m0 = blockIdx.y * BM;                                                 \
    const int n0 = blockIdx.x * BN;                                                 \
    const int m_off = (wid & 1) * 64;                                               \
    const int n_off = (wid >> 1) * 64;                                              \
    const __half* aS[2] = { Ahi + (size_t)m0 * K, Alo + (size_t)m0 * K };           \
    const __half* bSrc  = Bh + (size_t)n0 * K;                                      \
    const int NIT = K / BK;                                                         \
    auto load_stage = [&](int sbuf, int k0) {                                       \
        uint32_t stg = sbase + sbuf * STAGE2_B;                                     \
        _Pragma("unroll")                                                           \
        for (int p = 0; p < 2; p++) {                                               \
            uint32_t part = stg + p * A_BYTES;                                      \
            const __half* src = aS[p] + k0;                                         \
            _Pragma("unroll")                                                       \
            for (int r = 0; r < 4; r++) {                                           \
                int idx = r * 128 + tid;                                            \
                int row = idx >> 2, cch = idx & 3;                                  \
                uint32_t soff = SWZ64((uint32_t)(row * 64 + cch * 16));             \
                CP_ASYNC16(part + soff, src + (size_t)row * K + cch * 8);           \
            }                                                                       \
        }                                                                           \
        {                                                                           \
            uint32_t part = stg + 2 * A_BYTES;                                      \
            const __half* src = bSrc + k0;                                          \
            _Pragma("unroll")                                                       \
            for (int r = 0; r < 4; r++) {                                           \
                int idx = r * 128 + tid;                                            \
                int row = idx >> 2, cch = idx & 3;                                  \
                uint32_t soff = SWZ64((uint32_t)(row * 64 + cch * 16));             \
                CP_ASYNC16(part + soff, src + (size_t)row * K + cch * 8);           \
            }                                                                       \
        }                                                                           \
    };                                                                              \
    float c[4][8][4];                                                               \
    _Pragma("unroll")                                                               \
    for (int i = 0; i < 4; i++)                                                     \
        _Pragma("unroll")                                                           \
        for (int j = 0; j < 8; j++)                                                 \
            _Pragma("unroll")                                                       \
            for (int t = 0; t < 4; t++) c[i][j][t] = 0.f;                           \
    load_stage(0, 0); CP_COMMIT();                                                  \
    load_stage(1, BK); CP_COMMIT();                                                 \
    const int lr = lane & 15;                                                       \
    const int lk = lane >> 4;                                                       \
    int sbuf = 0;                                                                   \
    for (int it = 0; it < NIT; it++) {                                              \
        CP_WAIT(1);                                                                 \
        __syncthreads();                                                            \
        if (it + 2 < NIT) { load_stage((sbuf + 2) % 3, (it + 2) * BK); CP_COMMIT(); } \
        uint32_t stg  = sbase + sbuf * STAGE2_B;                                    \
        uint32_t aHiB = stg;                                                        \
        uint32_t aLoB = stg + A_BYTES;                                              \
        uint32_t bHiB = stg + 2 * A_BYTES;                                          \
        _Pragma("unroll")                                                           \
        for (int ks = 0; ks < 2; ks++) {                                            \
            uint32_t ahi[4][4], alo[4][4];                                          \
            _Pragma("unroll")                                                       \
            for (int mi = 0; mi < 4; mi++) {                                        \
                uint32_t sw = SWZ64((uint32_t)((m_off + mi * 16 + lr) * 64 + ks * 32 + lk * 16)); \
                LDSM_X4(ahi[mi][0], ahi[mi][1], ahi[mi][2], ahi[mi][3], aHiB + sw); \
                LDSM_X4(alo[mi][0], alo[mi][1], alo[mi][2], alo[mi][3], aLoB + sw); \
            }                                                                       \
            _Pragma("unroll")                                                       \
            for (int ng = 0; ng < 4; ng++) {                                        \
                uint32_t sw = SWZ64((uint32_t)((n_off + ng * 16 + lr) * 64 + ks * 32 + lk * 16)); \
                uint32_t bh0, bh1, bh2, bh3;                                        \
                LDSM_X4(bh0, bh1, bh2, bh3, bHiB + sw);                             \
                _Pragma("unroll")                                                   \
                for (int mi = 0; mi < 4; mi++) {                                    \
                    MMAF16(c[mi][ng*2+0], ahi[mi], bh0, bh2);                       \
                    MMAF16(c[mi][ng*2+1], ahi[mi], bh1, bh3);                       \
                    MMAF16(c[mi][ng*2+0], alo[mi], bh0, bh2);                       \
                    MMAF16(c[mi][ng*2+1], alo[mi], bh1, bh3);                       \
                }                                                                   \
            }                                                                       \
        }                                                                           \
        sbuf = (sbuf + 1) % 3;                                                      \
    }                                                                               \
    const int cr = lane >> 2;                                                       \
    const int cc = (lane & 3) * 2;

// ---- 1-term mainloop (A hi, B hi) -> c[4][8][4] ----
#define STAGE1_B (A_BYTES + B_BYTES)       // 16384
#define GEMM1T_SMEM (3 * STAGE1_B)         // 49152

#define GEMM_MAINLOOP_1T(Ahi, Bh, K)                                                \
    extern __shared__ __align__(1024) char smem[];                                  \
    const uint32_t sbase = smem_u32(smem);                                          \
    const int tid  = threadIdx.x;                                                   \
    const int wid  = tid >> 5;                                                      \
    const int lane = tid & 31;                                                      \
    const int m0 = blockIdx.y * BM;                                                 \
    const int n0 = blockIdx.x * BN;                                                 \
    const int m_off = (wid & 1) * 64;                                               \
    const int n_off = (wid >> 1) * 64;                                              \
    const __half* aSrc = Ahi + (size_t)m0 * K;                                      \
    const __half* bSrc = Bh + (size_t)n0 * K;                                       \
    const int NIT = K / BK;                                                         \
    auto load_stage = [&](int sbuf, int k0) {                                       \
        uint32_t stg = sbase + sbuf * STAGE1_B;                                     \
        _Pragma("unroll")                                                           \
        for (int r = 0; r < 4; r++) {                                               \
            int idx = r * 128 + tid;                                                \
            int row = idx >> 2, cch = idx & 3;                                      \
            uint32_t soff = SWZ64((uint32_t)(row * 64 + cch * 16));                 \
            CP_ASYNC16(stg + soff, aSrc + k0 + (size_t)row * K + cch * 8);          \
        }                                                                           \
        _Pragma("unroll")                                                           \
        for (int r = 0; r < 4; r++) {                                               \
            int idx = r * 128 + tid;                                                \
            int row = idx >> 2, cch = idx & 3;                                      \
            uint32_t soff = SWZ64((uint32_t)(row * 64 + cch * 16));                 \
            CP_ASYNC16(stg + A_BYTES + soff, bSrc + k0 + (size_t)row * K + cch * 8);\
        }                                                                           \
    };                                                                              \
    float c[4][8][4];                                                               \
    _Pragma("unroll")                                                               \
    for (int i = 0; i < 4; i++)                                                     \
        _Pragma("unroll")                                                           \
        for (int j = 0; j < 8; j++)                                                 \
            _Pragma("unroll")                                                       \
            for (int t = 0; t < 4; t++) c[i][j][t] = 0.f;                           \
    load_stage(0, 0); CP_COMMIT();                                                  \
    load_stage(1, BK); CP_COMMIT();                                                 \
    const int lr = lane & 15;                                                       \
    const int lk = lane >> 4;                                                       \
    int sbuf = 0;                                                                   \
    for (int it = 0; it < NIT; it++) {                                              \
        CP_WAIT(1);                                                                 \
        __syncthreads();                                                            \
        if (it + 2 < NIT) { load_stage((sbuf + 2) % 3, (it + 2) * BK); CP_COMMIT(); } \
        uint32_t stg  = sbase + sbuf * STAGE1_B;                                    \
        uint32_t aHiB = stg;                                                        \
        uint32_t bHiB = stg + A_BYTES;                                              \
        _Pragma("unroll")                                                           \
        for (int ks = 0; ks < 2; ks++) {                                            \
            uint32_t ahi[4][4];                                                     \
            _Pragma("unroll")                                                       \
            for (int mi = 0; mi < 4; mi++) {                                        \
                uint32_t sw = SWZ64((uint32_t)((m_off + mi * 16 + lr) * 64 + ks * 32 + lk * 16)); \
                LDSM_X4(ahi[mi][0], ahi[mi][1], ahi[mi][2], ahi[mi][3], aHiB + sw); \
            }                                                                       \
            _Pragma("unroll")                                                       \
            for (int ng = 0; ng < 4; ng++) {                                        \
                uint32_t sw = SWZ64((uint32_t)((n_off + ng * 16 + lr) * 64 + ks * 32 + lk * 16)); \
                uint32_t bh0, bh1, bh2, bh3;                                        \
                LDSM_X4(bh0, bh1, bh2, bh3, bHiB + sw);                             \
                _Pragma("unroll")                                                   \
                for (int mi = 0; mi < 4; mi++) {                                    \
                    MMAF16(c[mi][ng*2+0], ahi[mi], bh0, bh2);                       \
                    MMAF16(c[mi][ng*2+1], ahi[mi], bh1, bh3);                       \
                }                                                                   \
            }                                                                       \
        }                                                                           \
        sbuf = (sbuf + 1) % 3;                                                      \
    }                                                                               \
    const int cr = lane >> 2;                                                       \
    const int cc = (lane & 3) * 2;

// ---------------------------------------------------------------------------
// GEMM1: qkv projection (2-term), epilogue -> Q(hi/lo, scaled), K(hi), V(hi)
// ---------------------------------------------------------------------------
__global__ __launch_bounds__(128, 2)
void gemm_qkv(const __half* __restrict__ Ahi, const __half* __restrict__ Alo,
              const __half* __restrict__ Bh,
              __half* __restrict__ qhi, __half* __restrict__ qlo,
              __half* __restrict__ khi, __half* __restrict__ vhi)
{
    GEMM_MAINLOOP_2T(Ahi, Alo, Bh, DIM)

    const int seg  = n0 >> 10;           // 0=Q, 1=K, 2=V
    const int col0 = (n0 & 1023) + n_off;
#pragma unroll
    for (int mi = 0; mi < 4; mi++) {
        int r0 = m0 + m_off + mi * 16 + cr;
#pragma unroll
        for (int j = 0; j < 8; j++) {
            int col = col0 + j * 8 + cc;
#pragma unroll
            for (int half = 0; half < 2; half++) {
                int row = r0 + half * 8;
                float v0 = c[mi][j][half * 2 + 0];
                float v1 = c[mi][j][half * 2 + 1];
                size_t off = (size_t)row * DIM + col;
                if (seg == 0) {
                    v0 *= 0.125f; v1 *= 0.125f;
                    __half h0 = __float2half(v0), h1 = __float2half(v1);
                    *(uint32_t*)(qhi + off) = pack_h2(v0, v1);
                    *(uint32_t*)(qlo + off) =
                        pack_h2(v0 - __half2float(h0), v1 - __half2float(h1));
                } else if (seg == 1) {
                    *(uint32_t*)(khi + off) = pack_h2(v0, v1);
                } else {
                    *(uint32_t*)(vhi + off) = pack_h2(v0, v1);
                }
            }
        }
    }
}

// ---------------------------------------------------------------------------
// GEMM2: out projection, 1-term (A hi only), fp32 out
// ---------------------------------------------------------------------------
__global__ __launch_bounds__(128, 2)
void gemm_out(const __half* __restrict__ Ahi, const __half* __restrict__ Bh,
              float* __restrict__ C)
{
    GEMM_MAINLOOP_1T(Ahi, Bh, DIM)

#pragma unroll
    for (int mi = 0; mi < 4; mi++) {
        int r0 = m0 + m_off + mi * 16 + cr;
#pragma unroll
        for (int j = 0; j < 8; j++) {
            int col = n0 + n_off + j * 8 + cc;
            *(float2*)(C + (size_t)r0 * DIM + col)       = make_float2(c[mi][j][0], c[mi][j][1]);
            *(float2*)(C + (size_t)(r0 + 8) * DIM + col) = make_float2(c[mi][j][2], c[mi][j][3]);
        }
    }
}

// ---------------------------------------------------------------------------
// Tensor-core flash attention: S = (Qhi+Qlo)·Khi (2-term); PV 1-term (P hi).
// ALiBi + causal. fp16 in; fp16 hi out only.
// smem: Q_HI 0 (16384), Q_LO 16384, stages at 32768 (Khi+Vhi 16384) x2,
//       P_HI 65536 -> 81920 total
// ---------------------------------------------------------------------------
#define ATT_SMEM 81920
#define Q_HI 0
#define Q_LO 16384
#define STG0 32768
#define P_HI 65536

__global__ __launch_bounds__(256, 2)
void attn_mma(const __half* __restrict__ qhi, const __half* __restrict__ qlo,
              const __half* __restrict__ khi, const __half* __restrict__ vhi,
              __half* __restrict__ out_hi)
{
    extern __shared__ __align__(1024) char smem[];
    const uint32_t sbase = smem_u32(smem);
    const int tid  = threadIdx.x;
    const int wid  = tid >> 5;
    const int lane = tid & 31;
    const int lr   = lane & 15;
    const int lk   = lane >> 4;

    const int qt = (int)(gridDim.x - 1 - blockIdx.x);   // largest tiles first
    const int bh = blockIdx.y;
    const int b  = bh >> 4;
    const int h  = bh & 15;
    const int q0 = qt * 128;

    const float slope = exp2f(-0.5f * (float)(h + 1));

    const __half* qh_base = qhi + (size_t)(b * SEQ) * DIM + h * HD;
    const __half* ql_base = qlo + (size_t)(b * SEQ) * DIM + h * HD;
    const __half* kh_base = khi + (size_t)(b * SEQ) * DIM + h * HD;
    const __half* vh_base = vhi + (size_t)(b * SEQ) * DIM + h * HD;

    // ---- issue Q tile loads (128 rows x 128 B, hi + lo) ----
#pragma unroll
    for (int r = 0; r < 4; r++) {
        int idx = r * 256 + tid;
        int row = idx >> 3;
        int ch  = idx & 7;
        uint32_t soff = SWZ128((uint32_t)(row * 128 + ch * 16));
        CP_ASYNC16(sbase + Q_HI + soff, qh_base + (size_t)(q0 + row) * DIM + ch * 8);
        CP_ASYNC16(sbase + Q_LO + soff, ql_base + (size_t)(q0 + row) * DIM + ch * 8);
    }

    const int nkt = 2 * qt + 2;

    auto issue_kv = [&](int kt, int s) {
        uint32_t stg = sbase + STG0 + s * 16384;
        int k0 = kt * 64;
#pragma unroll
        for (int r = 0; r < 2; r++) {
            int idx = r * 256 + tid;
            int row = idx >> 3;
            int ch  = idx & 7;
            uint32_t soff = SWZ128((uint32_t)(row * 128 + ch * 16));
            CP_ASYNC16(stg + soff,        kh_base + (size_t)(k0 + row) * DIM + ch * 8);
            CP_ASYNC16(stg + 8192 + soff, vh_base + (size_t)(k0 + row) * DIM + ch * 8);
        }
    };

    issue_kv(0, 0);
    CP_COMMIT();

    float cs[8][4];
    float co[8][4];
#pragma unroll
    for (int j = 0; j < 8; j++)
#pragma unroll
        for (int t = 0; t < 4; t++) co[j][t] = 0.f;

    float m0v = -1e30f, m1v = -1e30f, l0v = 0.f, l1v = 0.f;

    const int r0 = lane >> 2;
    const int ccol = (lane & 3) * 2;
    const int gi0 = q0 + wid * 16 + r0;
    const int gi1 = gi0 + 8;

    for (int kt = 0; kt < nkt; kt++) {
        const int s = kt & 1;
        const int k0 = kt * 64;
        const uint32_t stgo = STG0 + s * 16384;

        __syncthreads();
        if (kt + 1 < nkt) {
            issue_kv(kt + 1, s ^ 1);
            CP_COMMIT();
            CP_WAIT(1);
        } else {
            CP_WAIT(0);
        }
        __syncthreads();

        // ---- S = Q K^T (2-term on Q) ----
#pragma unroll
        for (int j = 0; j < 8; j++)
#pragma unroll
            for (int t = 0; t < 4; t++) cs[j][t] = 0.f;

        uint32_t kHiB = sbase + stgo;
#pragma unroll
        for (int ks = 0; ks < 4; ks++) {
            uint32_t qoff = SWZ128((uint32_t)((wid * 16 + lr) * 128 + ks * 32 + lk * 16));
            uint32_t ahi[4], alo[4];
            LDSM_X4(ahi[0], ahi[1], ahi[2], ahi[3], sbase + Q_HI + qoff);
            LDSM_X4(alo[0], alo[1], alo[2], alo[3], sbase + Q_LO + qoff);
#pragma unroll
            for (int ng = 0; ng < 4; ng++) {
                uint32_t boff = SWZ128((uint32_t)((ng * 16 + lr) * 128 + ks * 32 + lk * 16));
                uint32_t bh0, bh1, bh2, bh3;
                LDSM_X4(bh0, bh1, bh2, bh3, kHiB + boff);
                MMAF16(cs[ng*2+0], ahi, bh0, bh2);
                MMAF16(cs[ng*2+1], ahi, bh1, bh3);
                MMAF16(cs[ng*2+0], alo, bh0, bh2);
                MMAF16(cs[ng*2+1], alo, bh1, bh3);
            }
        }

        // ---- ALiBi + causal mask ----
#pragma unroll
        for (int nb = 0; nb < 8; nb++) {
#pragma unroll
            for (int cidx = 0; cidx < 2; cidx++) {
                int gj = k0 + nb * 8 + ccol + cidx;
                float rel0 = slope * (float)(gj - gi0);
                float rel1 = slope * (float)(gj - gi1);
                cs[nb][cidx]     = (gj > gi0) ? -1e30f : cs[nb][cidx]     - rel0;
                cs[nb][2 + cidx] = (gj > gi1) ? -1e30f : cs[nb][2 + cidx] - rel1;
            }
        }

        // ---- online softmax ----
        float mx0 = -1e30f, mx1 = -1e30f;
#pragma unroll
        for (int nb = 0; nb < 8; nb++) {
            mx0 = fmaxf(mx0, fmaxf(cs[nb][0], cs[nb][1]));
            mx1 = fmaxf(mx1, fmaxf(cs[nb][2], cs[nb][3]));
        }
        mx0 = fmaxf(mx0, __shfl_xor_sync(0xffffffff, mx0, 1));
        mx0 = fmaxf(mx0, __shfl_xor_sync(0xffffffff, mx0, 2));
        mx1 = fmaxf(mx1, __shfl_xor_sync(0xffffffff, mx1, 1));
        mx1 = fmaxf(mx1, __shfl_xor_sync(0xffffffff, mx1, 2));

        float mn0 = fmaxf(m0v, mx0), mn1 = fmaxf(m1v, mx1);
        float corr0 = __expf(m0v - mn0), corr1 = __expf(m1v - mn1);
        m0v = mn0; m1v = mn1;

        float sum0 = 0.f, sum1 = 0.f;
        const int prow0 = wid * 16 + r0;
#pragma unroll
        for (int nb = 0; nb < 8; nb++) {
            float p00 = __expf(cs[nb][0] - mn0);
            float p01 = __expf(cs[nb][1] - mn0);
            float p10 = __expf(cs[nb][2] - mn1);
            float p11 = __expf(cs[nb][3] - mn1);
            sum0 += p00 + p01;
            sum1 += p10 + p11;
            uint32_t off0 = SWZ128((uint32_t)(prow0 * 128 + nb * 16 + (lane & 3) * 4));
            uint32_t off1 = SWZ128((uint32_t)((prow0 + 8) * 128 + nb * 16 + (lane & 3) * 4));
            *(uint32_t*)(smem + P_HI + off0) = pack_h2(p00, p01);
            *(uint32_t*)(smem + P_HI + off1) = pack_h2(p10, p11);
        }
        sum0 += __shfl_xor_sync(0xffffffff, sum0, 1);
        sum0 += __shfl_xor_sync(0xffffffff, sum0, 2);
        sum1 += __shfl_xor_sync(0xffffffff, sum1, 1);
        sum1 += __shfl_xor_sync(0xffffffff, sum1, 2);
        l0v = l0v * corr0 + sum0;
        l1v = l1v * corr1 + sum1;

#pragma unroll
        for (int nb = 0; nb < 8; nb++) {
            co[nb][0] *= corr0; co[nb][1] *= corr0;
            co[nb][2] *= corr1; co[nb][3] *= corr1;
        }
        __syncwarp();

        // ---- O += P V (1-term, P hi; V via ldmatrix.trans) ----
        uint32_t vHiB = sbase + stgo + 8192;
#pragma unroll
        for (int ks = 0; ks < 4; ks++) {
            uint32_t poff = SWZ128((uint32_t)((wid * 16 + lr) * 128 + ks * 32 + lk * 16));
            uint32_t phi[4];
            LDSM_X4(phi[0], phi[1], phi[2], phi[3], sbase + P_HI + poff);
#pragma unroll
            for (int ng = 0; ng < 4; ng++) {
                uint32_t voff = SWZ128((uint32_t)((ks * 16 + lr) * 128 + ng * 32 + lk * 16));
                uint32_t vh0, vh1, vh2, vh3;
                LDSM_X4_T(vh0, vh1, vh2, vh3, vHiB + voff);
                MMAF16(co[ng*2+0], phi, vh0, vh1);
                MMAF16(co[ng*2+1], phi, vh2, vh3);
            }
        }
    }

    // ---- normalize + write fp16 hi ----
    float inv0 = 1.0f / l0v, inv1 = 1.0f / l1v;
    size_t row0 = (size_t)(b * SEQ + gi0) * DIM + h * HD;
    size_t row1 = (size_t)(b * SEQ + gi1) * DIM + h * HD;
#pragma unroll
    for (int nb = 0; nb < 8; nb++) {
        int d = nb * 8 + ccol;
        *(uint32_t*)(out_hi + row0 + d) = pack_h2(co[nb][0] * inv0, co[nb][1] * inv0);
        *(uint32_t*)(out_hi + row1 + d) = pack_h2(co[nb][2] * inv1, co[nb][3] * inv1);
    }
}

// ---------------------------------------------------------------------------
extern "C" void kernel_launch(void* const* d_in, const int* in_sizes, int n_in,
                              void* d_out, int out_size)
{
    const float* x    = (const float*)d_in[0];
    const float* Wqkv = (const float*)d_in[1];
    const float* Wo   = (const float*)d_in[2];
    float* out = (float*)d_out;

    __half *xhi, *xlo, *wqh, *woh, *qhi, *qlo, *khi, *vhi, *ahi;
    cudaGetSymbolAddress((void**)&xhi, g_xhi);
    cudaGetSymbolAddress((void**)&xlo, g_xlo);
    cudaGetSymbolAddress((void**)&wqh, g_wqh);
    cudaGetSymbolAddress((void**)&woh, g_woh);
    cudaGetSymbolAddress((void**)&qhi, g_qhi);
    cudaGetSymbolAddress((void**)&qlo, g_qlo);
    cudaGetSymbolAddress((void**)&khi, g_khi);
    cudaGetSymbolAddress((void**)&vhi, g_vhi);
    cudaGetSymbolAddress((void**)&ahi, g_ahi);

    cudaFuncSetAttribute(gemm_qkv, cudaFuncAttributeMaxDynamicSharedMemorySize, GEMM2T_SMEM);
    cudaFuncSetAttribute(gemm_out, cudaFuncAttributeMaxDynamicSharedMemorySize, GEMM1T_SMEM);
    cudaFuncSetAttribute(attn_mma, cudaFuncAttributeMaxDynamicSharedMemorySize, ATT_SMEM);

    // fused hi/lo splits (x) + hi conversions (weights)
    {
        int n4 = N4_X + N4_WQ + N4_WO;
        split_all<<<(n4 + 255) / 256, 256>>>(x, xhi, xlo, Wqkv, wqh, Wo, woh);
    }

    // 1) qkv projection -> fp16 Q(hi/lo, scaled), K(hi), V(hi)
    {
        dim3 grid(3 * DIM / BN, NTOK / BM);   // (24, 32)
        gemm_qkv<<<grid, 128, GEMM2T_SMEM>>>(xhi, xlo, wqh, qhi, qlo, khi, vhi);
    }

    // 2) tensor-core flash attention (fp16 in, fp16 hi out)
    {
        dim3 grid(SEQ / 128, BATCH * HEADS);   // (16, 32)
        attn_mma<<<grid, 256, ATT_SMEM>>>(qhi, qlo, khi, vhi, ahi);
    }

    // 3) out = attn_hi @ Wo^T (1-term, fp32 out)
    {
        dim3 grid(DIM / BN, NTOK / BM);        // (8, 32)
        gemm_out<<<grid, 128, GEMM1T_SMEM>>>(ahi, woh, out);
    }
}

// round 12
// speedup vs baseline: 1.2733x; 1.0726x over previous
#include <cuda_runtime.h>
#include <cuda_fp16.h>
#include <cstdint>

// Problem constants
#define BATCH 2
#define SEQ   2048
#define DIM   1024
#define HEADS 16
#define HD    64
#define NTOK  (BATCH*SEQ)   // 4096

// ---------------------------------------------------------------------------
// Scratch (__device__ globals; allocation-free rule)
// ---------------------------------------------------------------------------
__device__ __half g_xhi[(size_t)NTOK * DIM];
__device__ __half g_xlo[(size_t)NTOK * DIM];
__device__ __half g_wqh[(size_t)3 * DIM * DIM];     // weights: hi only
__device__ __half g_woh[(size_t)DIM * DIM];
__device__ __half g_qhi[(size_t)NTOK * DIM];        // Q (pre-scaled) hi
__device__ __half g_qlo[(size_t)NTOK * DIM];        // Q lo
__device__ __half g_khi[(size_t)NTOK * DIM];        // K hi
__device__ __half g_vhi[(size_t)NTOK * DIM];        // V hi
__device__ __half g_ahi[(size_t)NTOK * DIM];        // attn out hi

// ---------------------------------------------------------------------------
// PTX helpers (baseline sm_100-safe)
// ---------------------------------------------------------------------------
__device__ __forceinline__ uint32_t smem_u32(const void* p) {
    uint32_t a;
    asm("{ .reg .u64 t; cvta.to.shared.u64 t, %1; cvt.u32.u64 %0, t; }" : "=r"(a) : "l"(p));
    return a;
}
#define SWZ64(off)  ((off) ^ (((off) >> 3) & 0x30))
#define SWZ128(off) ((off) ^ (((off) >> 3) & 0x70))

#define CP_ASYNC16(saddr, gptr) \
    asm volatile("cp.async.cg.shared.global [%0], [%1], 16;\n" :: "r"(saddr), "l"(gptr))
#define CP_COMMIT() asm volatile("cp.async.commit_group;\n" ::: "memory")
#define CP_WAIT(N)  asm volatile("cp.async.wait_group %0;\n" :: "n"(N) : "memory")

#define LDSM_X4(r0, r1, r2, r3, addr) \
    asm volatile("ldmatrix.sync.aligned.m8n8.x4.shared.b16 {%0,%1,%2,%3}, [%4];" \
                 : "=r"(r0), "=r"(r1), "=r"(r2), "=r"(r3) : "r"(addr))
#define LDSM_X4_T(r0, r1, r2, r3, addr) \
    asm volatile("ldmatrix.sync.aligned.m8n8.x4.trans.shared.b16 {%0,%1,%2,%3}, [%4];" \
                 : "=r"(r0), "=r"(r1), "=r"(r2), "=r"(r3) : "r"(addr))

#define MMAF16(c, a, b0, b1) \
    asm volatile("mma.sync.aligned.m16n8k16.row.col.f32.f16.f16.f32 " \
                 "{%0,%1,%2,%3}, {%4,%5,%6,%7}, {%8,%9}, {%0,%1,%2,%3};" \
                 : "+f"((c)[0]), "+f"((c)[1]), "+f"((c)[2]), "+f"((c)[3]) \
                 : "r"((a)[0]), "r"((a)[1]), "r"((a)[2]), "r"((a)[3]), \
                   "r"(b0), "r"(b1))

__device__ __forceinline__ uint32_t pack_h2(float a, float b) {
    __half2 v(__float2half(a), __float2half(b));
    return *(uint32_t*)&v;
}

// ---------------------------------------------------------------------------
// fused split kernel: x -> hi/lo; weights -> hi only
// ---------------------------------------------------------------------------
#define N4_X  (NTOK * DIM / 4)
#define N4_WQ (3 * DIM * DIM / 4)
#define N4_WO (DIM * DIM / 4)

__global__ void split_all(const float* __restrict__ x,  __half* __restrict__ xhi, __half* __restrict__ xlo,
                          const float* __restrict__ wq, __half* __restrict__ wqh,
                          const float* __restrict__ wo, __half* __restrict__ woh)
{
    int i = blockIdx.x * blockDim.x + threadIdx.x;
    if (i < N4_X) {
        float4 v = ((const float4*)x)[i];
        __half h0 = __float2half(v.x), h1 = __float2half(v.y);
        __half h2 = __float2half(v.z), h3 = __float2half(v.w);
        __half2* hp = (__half2*)(xhi + (size_t)i * 4);
        __half2* lp = (__half2*)(xlo + (size_t)i * 4);
        hp[0] = __half2(h0, h1);
        hp[1] = __half2(h2, h3);
        lp[0] = __half2(__float2half(v.x - __half2float(h0)),
                        __float2half(v.y - __half2float(h1)));
        lp[1] = __half2(__float2half(v.z - __half2float(h2)),
                        __float2half(v.w - __half2float(h3)));
        return;
    }
    int j = i - N4_X;
    const float* src; __half* dst;
    if (j < N4_WQ) { src = wq; dst = wqh; }
    else if (j < N4_WQ + N4_WO) { j -= N4_WQ; src = wo; dst = woh; }
    else return;
    float4 v = ((const float4*)src)[j];
    __half2* hp = (__half2*)(dst + (size_t)j * 4);
    hp[0] = __half2(__float2half(v.x), __float2half(v.y));
    hp[1] = __half2(__float2half(v.z), __float2half(v.w));
}

// ---------------------------------------------------------------------------
// GEMM common tile constants
// ---------------------------------------------------------------------------
#define BM 128
#define BN 128
#define BK 32
#define A_BYTES (BM * BK * 2)              // 8192 per term
#define B_BYTES (BN * BK * 2)              // 8192 (hi only)
#define STAGE2_B (2*A_BYTES + B_BYTES)     // 24576
#define GEMM2T_SMEM (3 * STAGE2_B)         // 73728
#define STAGE1_B (A_BYTES + B_BYTES)       // 16384
#define GEMM1T_SMEM (3 * STAGE1_B)         // 49152

// ---------------------------------------------------------------------------
// GEMM1: qkv projection. Q columns (n0<1024): 2-term (x hi+lo). K/V columns:
// 1-term (x hi only) — their fp16 storage rounding dominates anyway.
// Epilogue -> Q(hi/lo, scaled), K(hi), V(hi).
// ---------------------------------------------------------------------------
__global__ __launch_bounds__(128, 2)
void gemm_qkv(const __half* __restrict__ Ahi, const __half* __restrict__ Alo,
              const __half* __restrict__ Bh,
              __half* __restrict__ qhi, __half* __restrict__ qlo,
              __half* __restrict__ khi, __half* __restrict__ vhi)
{
    extern __shared__ __align__(1024) char smem[];
    const uint32_t sbase = smem_u32(smem);
    const int tid  = threadIdx.x;
    const int wid  = tid >> 5;
    const int lane = tid & 31;
    const int m0 = blockIdx.y * BM;
    const int n0 = blockIdx.x * BN;
    const int m_off = (wid & 1) * 64;
    const int n_off = (wid >> 1) * 64;
    const int seg = n0 >> 10;               // 0=Q, 1=K, 2=V
    const bool do_lo = (seg == 0);

    const __half* aHiS = Ahi + (size_t)m0 * DIM;
    const __half* aLoS = Alo + (size_t)m0 * DIM;
    const __half* bSrc = Bh + (size_t)n0 * DIM;

    const int NIT = DIM / BK;               // 32

    auto load_stage = [&](int sbuf, int k0) {
        uint32_t stg = sbase + sbuf * STAGE2_B;
#pragma unroll
        for (int r = 0; r < 4; r++) {
            int idx = r * 128 + tid;
            int row = idx >> 2, cch = idx & 3;
            uint32_t soff = SWZ64((uint32_t)(row * 64 + cch * 16));
            CP_ASYNC16(stg + soff, aHiS + k0 + (size_t)row * DIM + cch * 8);
        }
        if (do_lo) {
#pragma unroll
            for (int r = 0; r < 4; r++) {
                int idx = r * 128 + tid;
                int row = idx >> 2, cch = idx & 3;
                uint32_t soff = SWZ64((uint32_t)(row * 64 + cch * 16));
                CP_ASYNC16(stg + A_BYTES + soff, aLoS + k0 + (size_t)row * DIM + cch * 8);
            }
        }
#pragma unroll
        for (int r = 0; r < 4; r++) {
            int idx = r * 128 + tid;
            int row = idx >> 2, cch = idx & 3;
            uint32_t soff = SWZ64((uint32_t)(row * 64 + cch * 16));
            CP_ASYNC16(stg + 2 * A_BYTES + soff, bSrc + k0 + (size_t)row * DIM + cch * 8);
        }
    };

    float c[4][8][4];
#pragma unroll
    for (int i = 0; i < 4; i++)
#pragma unroll
        for (int j = 0; j < 8; j++)
#pragma unroll
            for (int t = 0; t < 4; t++) c[i][j][t] = 0.f;

    load_stage(0, 0); CP_COMMIT();
    load_stage(1, BK); CP_COMMIT();

    const int lr = lane & 15;
    const int lk = lane >> 4;

    int sbuf = 0;
    for (int it = 0; it < NIT; it++) {
        CP_WAIT(1);
        __syncthreads();
        if (it + 2 < NIT) { load_stage((sbuf + 2) % 3, (it + 2) * BK); CP_COMMIT(); }

        uint32_t stg  = sbase + sbuf * STAGE2_B;
        uint32_t aHiB = stg;
        uint32_t aLoB = stg + A_BYTES;
        uint32_t bHiB = stg + 2 * A_BYTES;

#pragma unroll
        for (int ks = 0; ks < 2; ks++) {
            uint32_t ahi[4][4], alo[4][4];
#pragma unroll
            for (int mi = 0; mi < 4; mi++) {
                uint32_t sw = SWZ64((uint32_t)((m_off + mi * 16 + lr) * 64 + ks * 32 + lk * 16));
                LDSM_X4(ahi[mi][0], ahi[mi][1], ahi[mi][2], ahi[mi][3], aHiB + sw);
                if (do_lo) {
                    LDSM_X4(alo[mi][0], alo[mi][1], alo[mi][2], alo[mi][3], aLoB + sw);
                }
            }
#pragma unroll
            for (int ng = 0; ng < 4; ng++) {
                uint32_t sw = SWZ64((uint32_t)((n_off + ng * 16 + lr) * 64 + ks * 32 + lk * 16));
                uint32_t bh0, bh1, bh2, bh3;
                LDSM_X4(bh0, bh1, bh2, bh3, bHiB + sw);
#pragma unroll
                for (int mi = 0; mi < 4; mi++) {
                    MMAF16(c[mi][ng*2+0], ahi[mi], bh0, bh2);
                    MMAF16(c[mi][ng*2+1], ahi[mi], bh1, bh3);
                    if (do_lo) {
                        MMAF16(c[mi][ng*2+0], alo[mi], bh0, bh2);
                        MMAF16(c[mi][ng*2+1], alo[mi], bh1, bh3);
                    }
                }
            }
        }
        sbuf = (sbuf + 1) % 3;
    }

    const int cr = lane >> 2;
    const int cc = (lane & 3) * 2;
    const int col0 = (n0 & 1023) + n_off;
#pragma unroll
    for (int mi = 0; mi < 4; mi++) {
        int r0 = m0 + m_off + mi * 16 + cr;
#pragma unroll
        for (int j = 0; j < 8; j++) {
            int col = col0 + j * 8 + cc;
#pragma unroll
            for (int half = 0; half < 2; half++) {
                int row = r0 + half * 8;
                float v0 = c[mi][j][half * 2 + 0];
                float v1 = c[mi][j][half * 2 + 1];
                size_t off = (size_t)row * DIM + col;
                if (seg == 0) {
                    v0 *= 0.125f; v1 *= 0.125f;
                    __half h0 = __float2half(v0), h1 = __float2half(v1);
                    *(uint32_t*)(qhi + off) = pack_h2(v0, v1);
                    *(uint32_t*)(qlo + off) =
                        pack_h2(v0 - __half2float(h0), v1 - __half2float(h1));
                } else if (seg == 1) {
                    *(uint32_t*)(khi + off) = pack_h2(v0, v1);
                } else {
                    *(uint32_t*)(vhi + off) = pack_h2(v0, v1);
                }
            }
        }
    }
}

// ---------------------------------------------------------------------------
// GEMM2: out projection, 1-term (A hi only), fp32 out
// ---------------------------------------------------------------------------
__global__ __launch_bounds__(128, 2)
void gemm_out(const __half* __restrict__ Ahi, const __half* __restrict__ Bh,
              float* __restrict__ C)
{
    extern __shared__ __align__(1024) char smem[];
    const uint32_t sbase = smem_u32(smem);
    const int tid  = threadIdx.x;
    const int wid  = tid >> 5;
    const int lane = tid & 31;
    const int m0 = blockIdx.y * BM;
    const int n0 = blockIdx.x * BN;
    const int m_off = (wid & 1) * 64;
    const int n_off = (wid >> 1) * 64;
    const __half* aSrc = Ahi + (size_t)m0 * DIM;
    const __half* bSrc = Bh + (size_t)n0 * DIM;
    const int NIT = DIM / BK;

    auto load_stage = [&](int sbuf, int k0) {
        uint32_t stg = sbase + sbuf * STAGE1_B;
#pragma unroll
        for (int r = 0; r < 4; r++) {
            int idx = r * 128 + tid;
            int row = idx >> 2, cch = idx & 3;
            uint32_t soff = SWZ64((uint32_t)(row * 64 + cch * 16));
            CP_ASYNC16(stg + soff, aSrc + k0 + (size_t)row * DIM + cch * 8);
        }
#pragma unroll
        for (int r = 0; r < 4; r++) {
            int idx = r * 128 + tid;
            int row = idx >> 2, cch = idx & 3;
            uint32_t soff = SWZ64((uint32_t)(row * 64 + cch * 16));
            CP_ASYNC16(stg + A_BYTES + soff, bSrc + k0 + (size_t)row * DIM + cch * 8);
        }
    };

    float c[4][8][4];
#pragma unroll
    for (int i = 0; i < 4; i++)
#pragma unroll
        for (int j = 0; j < 8; j++)
#pragma unroll
            for (int t = 0; t < 4; t++) c[i][j][t] = 0.f;

    load_stage(0, 0); CP_COMMIT();
    load_stage(1, BK); CP_COMMIT();

    const int lr = lane & 15;
    const int lk = lane >> 4;

    int sbuf = 0;
    for (int it = 0; it < NIT; it++) {
        CP_WAIT(1);
        __syncthreads();
        if (it + 2 < NIT) { load_stage((sbuf + 2) % 3, (it + 2) * BK); CP_COMMIT(); }

        uint32_t stg  = sbase + sbuf * STAGE1_B;
        uint32_t aHiB = stg;
        uint32_t bHiB = stg + A_BYTES;

#pragma unroll
        for (int ks = 0; ks < 2; ks++) {
            uint32_t ahi[4][4];
#pragma unroll
            for (int mi = 0; mi < 4; mi++) {
                uint32_t sw = SWZ64((uint32_t)((m_off + mi * 16 + lr) * 64 + ks * 32 + lk * 16));
                LDSM_X4(ahi[mi][0], ahi[mi][1], ahi[mi][2], ahi[mi][3], aHiB + sw);
            }
#pragma unroll
            for (int ng = 0; ng < 4; ng++) {
                uint32_t sw = SWZ64((uint32_t)((n_off + ng * 16 + lr) * 64 + ks * 32 + lk * 16));
                uint32_t bh0, bh1, bh2, bh3;
                LDSM_X4(bh0, bh1, bh2, bh3, bHiB + sw);
#pragma unroll
                for (int mi = 0; mi < 4; mi++) {
                    MMAF16(c[mi][ng*2+0], ahi[mi], bh0, bh2);
                    MMAF16(c[mi][ng*2+1], ahi[mi], bh1, bh3);
                }
            }
        }
        sbuf = (sbuf + 1) % 3;
    }

    const int cr = lane >> 2;
    const int cc = (lane & 3) * 2;
#pragma unroll
    for (int mi = 0; mi < 4; mi++) {
        int r0 = m0 + m_off + mi * 16 + cr;
#pragma unroll
        for (int j = 0; j < 8; j++) {
            int col = n0 + n_off + j * 8 + cc;
            *(float2*)(C + (size_t)r0 * DIM + col)       = make_float2(c[mi][j][0], c[mi][j][1]);
            *(float2*)(C + (size_t)(r0 + 8) * DIM + col) = make_float2(c[mi][j][2], c[mi][j][3]);
        }
    }
}

// ---------------------------------------------------------------------------
// Tensor-core flash attention: S = (Qhi+Qlo)·Khi (2-term); PV 1-term (P hi).
// ALiBi + causal. fp16 in; fp16 hi out only. (unchanged from round 11)
// ---------------------------------------------------------------------------
#define ATT_SMEM 81920
#define Q_HI 0
#define Q_LO 16384
#define STG0 32768
#define P_HI 65536

__global__ __launch_bounds__(256, 2)
void attn_mma(const __half* __restrict__ qhi, const __half* __restrict__ qlo,
              const __half* __restrict__ khi, const __half* __restrict__ vhi,
              __half* __restrict__ out_hi)
{
    extern __shared__ __align__(1024) char smem[];
    const uint32_t sbase = smem_u32(smem);
    const int tid  = threadIdx.x;
    const int wid  = tid >> 5;
    const int lane = tid & 31;
    const int lr   = lane & 15;
    const int lk   = lane >> 4;

    const int qt = (int)(gridDim.x - 1 - blockIdx.x);   // largest tiles first
    const int bh = blockIdx.y;
    const int b  = bh >> 4;
    const int h  = bh & 15;
    const int q0 = qt * 128;

    const float slope = exp2f(-0.5f * (float)(h + 1));

    const __half* qh_base = qhi + (size_t)(b * SEQ) * DIM + h * HD;
    const __half* ql_base = qlo + (size_t)(b * SEQ) * DIM + h * HD;
    const __half* kh_base = khi + (size_t)(b * SEQ) * DIM + h * HD;
    const __half* vh_base = vhi + (size_t)(b * SEQ) * DIM + h * HD;

#pragma unroll
    for (int r = 0; r < 4; r++) {
        int idx = r * 256 + tid;
        int row = idx >> 3;
        int ch  = idx & 7;
        uint32_t soff = SWZ128((uint32_t)(row * 128 + ch * 16));
        CP_ASYNC16(sbase + Q_HI + soff, qh_base + (size_t)(q0 + row) * DIM + ch * 8);
        CP_ASYNC16(sbase + Q_LO + soff, ql_base + (size_t)(q0 + row) * DIM + ch * 8);
    }

    const int nkt = 2 * qt + 2;

    auto issue_kv = [&](int kt, int s) {
        uint32_t stg = sbase + STG0 + s * 16384;
        int k0 = kt * 64;
#pragma unroll
        for (int r = 0; r < 2; r++) {
            int idx = r * 256 + tid;
            int row = idx >> 3;
            int ch  = idx & 7;
            uint32_t soff = SWZ128((uint32_t)(row * 128 + ch * 16));
            CP_ASYNC16(stg + soff,        kh_base + (size_t)(k0 + row) * DIM + ch * 8);
            CP_ASYNC16(stg + 8192 + soff, vh_base + (size_t)(k0 + row) * DIM + ch * 8);
        }
    };

    issue_kv(0, 0);
    CP_COMMIT();

    float cs[8][4];
    float co[8][4];
#pragma unroll
    for (int j = 0; j < 8; j++)
#pragma unroll
        for (int t = 0; t < 4; t++) co[j][t] = 0.f;

    float m0v = -1e30f, m1v = -1e30f, l0v = 0.f, l1v = 0.f;

    const int r0 = lane >> 2;
    const int ccol = (lane & 3) * 2;
    const int gi0 = q0 + wid * 16 + r0;
    const int gi1 = gi0 + 8;

    for (int kt = 0; kt < nkt; kt++) {
        const int s = kt & 1;
        const int k0 = kt * 64;
        const uint32_t stgo = STG0 + s * 16384;

        __syncthreads();
        if (kt + 1 < nkt) {
            issue_kv(kt + 1, s ^ 1);
            CP_COMMIT();
            CP_WAIT(1);
        } else {
            CP_WAIT(0);
        }
        __syncthreads();

        // ---- S = Q K^T (2-term on Q) ----
#pragma unroll
        for (int j = 0; j < 8; j++)
#pragma unroll
            for (int t = 0; t < 4; t++) cs[j][t] = 0.f;

        uint32_t kHiB = sbase + stgo;
#pragma unroll
        for (int ks = 0; ks < 4; ks++) {
            uint32_t qoff = SWZ128((uint32_t)((wid * 16 + lr) * 128 + ks * 32 + lk * 16));
            uint32_t ahi[4], alo[4];
            LDSM_X4(ahi[0], ahi[1], ahi[2], ahi[3], sbase + Q_HI + qoff);
            LDSM_X4(alo[0], alo[1], alo[2], alo[3], sbase + Q_LO + qoff);
#pragma unroll
            for (int ng = 0; ng < 4; ng++) {
                uint32_t boff = SWZ128((uint32_t)((ng * 16 + lr) * 128 + ks * 32 + lk * 16));
                uint32_t bh0, bh1, bh2, bh3;
                LDSM_X4(bh0, bh1, bh2, bh3, kHiB + boff);
                MMAF16(cs[ng*2+0], ahi, bh0, bh2);
                MMAF16(cs[ng*2+1], ahi, bh1, bh3);
                MMAF16(cs[ng*2+0], alo, bh0, bh2);
                MMAF16(cs[ng*2+1], alo, bh1, bh3);
            }
        }

        // ---- ALiBi + causal mask ----
#pragma unroll
        for (int nb = 0; nb < 8; nb++) {
#pragma unroll
            for (int cidx = 0; cidx < 2; cidx++) {
                int gj = k0 + nb * 8 + ccol + cidx;
                float rel0 = slope * (float)(gj - gi0);
                float rel1 = slope * (float)(gj - gi1);
                cs[nb][cidx]     = (gj > gi0) ? -1e30f : cs[nb][cidx]     - rel0;
                cs[nb][2 + cidx] = (gj > gi1) ? -1e30f : cs[nb][2 + cidx] - rel1;
            }
        }

        // ---- online softmax ----
        float mx0 = -1e30f, mx1 = -1e30f;
#pragma unroll
        for (int nb = 0; nb < 8; nb++) {
            mx0 = fmaxf(mx0, fmaxf(cs[nb][0], cs[nb][1]));
            mx1 = fmaxf(mx1, fmaxf(cs[nb][2], cs[nb][3]));
        }
        mx0 = fmaxf(mx0, __shfl_xor_sync(0xffffffff, mx0, 1));
        mx0 = fmaxf(mx0, __shfl_xor_sync(0xffffffff, mx0, 2));
        mx1 = fmaxf(mx1, __shfl_xor_sync(0xffffffff, mx1, 1));
        mx1 = fmaxf(mx1, __shfl_xor_sync(0xffffffff, mx1, 2));

        float mn0 = fmaxf(m0v, mx0), mn1 = fmaxf(m1v, mx1);
        float corr0 = __expf(m0v - mn0), corr1 = __expf(m1v - mn1);
        m0v = mn0; m1v = mn1;

        float sum0 = 0.f, sum1 = 0.f;
        const int prow0 = wid * 16 + r0;
#pragma unroll
        for (int nb = 0; nb < 8; nb++) {
            float p00 = __expf(cs[nb][0] - mn0);
            float p01 = __expf(cs[nb][1] - mn0);
            float p10 = __expf(cs[nb][2] - mn1);
            float p11 = __expf(cs[nb][3] - mn1);
            sum0 += p00 + p01;
            sum1 += p10 + p11;
            uint32_t off0 = SWZ128((uint32_t)(prow0 * 128 + nb * 16 + (lane & 3) * 4));
            uint32_t off1 = SWZ128((uint32_t)((prow0 + 8) * 128 + nb * 16 + (lane & 3) * 4));
            *(uint32_t*)(smem + P_HI + off0) = pack_h2(p00, p01);
            *(uint32_t*)(smem + P_HI + off1) = pack_h2(p10, p11);
        }
        sum0 += __shfl_xor_sync(0xffffffff, sum0, 1);
        sum0 += __shfl_xor_sync(0xffffffff, sum0, 2);
        sum1 += __shfl_xor_sync(0xffffffff, sum1, 1);
        sum1 += __shfl_xor_sync(0xffffffff, sum1, 2);
        l0v = l0v * corr0 + sum0;
        l1v = l1v * corr1 + sum1;

#pragma unroll
        for (int nb = 0; nb < 8; nb++) {
            co[nb][0] *= corr0; co[nb][1] *= corr0;
            co[nb][2] *= corr1; co[nb][3] *= corr1;
        }
        __syncwarp();

        // ---- O += P V (1-term, P hi; V via ldmatrix.trans) ----
        uint32_t vHiB = sbase + stgo + 8192;
#pragma unroll
        for (int ks = 0; ks < 4; ks++) {
            uint32_t poff = SWZ128((uint32_t)((wid * 16 + lr) * 128 + ks * 32 + lk * 16));
            uint32_t phi[4];
            LDSM_X4(phi[0], phi[1], phi[2], phi[3], sbase + P_HI + poff);
#pragma unroll
            for (int ng = 0; ng < 4; ng++) {
                uint32_t voff = SWZ128((uint32_t)((ks * 16 + lr) * 128 + ng * 32 + lk * 16));
                uint32_t vh0, vh1, vh2, vh3;
                LDSM_X4_T(vh0, vh1, vh2, vh3, vHiB + voff);
                MMAF16(co[ng*2+0], phi, vh0, vh1);
                MMAF16(co[ng*2+1], phi, vh2, vh3);
            }
        }
    }

    // ---- normalize + write fp16 hi ----
    float inv0 = 1.0f / l0v, inv1 = 1.0f / l1v;
    size_t row0 = (size_t)(b * SEQ + gi0) * DIM + h * HD;
    size_t row1 = (size_t)(b * SEQ + gi1) * DIM + h * HD;
#pragma unroll
    for (int nb = 0; nb < 8; nb++) {
        int d = nb * 8 + ccol;
        *(uint32_t*)(out_hi + row0 + d) = pack_h2(co[nb][0] * inv0, co[nb][1] * inv0);
        *(uint32_t*)(out_hi + row1 + d) = pack_h2(co[nb][2] * inv1, co[nb][3] * inv1);
    }
}

// ---------------------------------------------------------------------------
extern "C" void kernel_launch(void* const* d_in, const int* in_sizes, int n_in,
                              void* d_out, int out_size)
{
    const float* x    = (const float*)d_in[0];
    const float* Wqkv = (const float*)d_in[1];
    const float* Wo   = (const float*)d_in[2];
    float* out = (float*)d_out;

    __half *xhi, *xlo, *wqh, *woh, *qhi, *qlo, *khi, *vhi, *ahi;
    cudaGetSymbolAddress((void**)&xhi, g_xhi);
    cudaGetSymbolAddress((void**)&xlo, g_xlo);
    cudaGetSymbolAddress((void**)&wqh, g_wqh);
    cudaGetSymbolAddress((void**)&woh, g_woh);
    cudaGetSymbolAddress((void**)&qhi, g_qhi);
    cudaGetSymbolAddress((void**)&qlo, g_qlo);
    cudaGetSymbolAddress((void**)&khi, g_khi);
    cudaGetSymbolAddress((void**)&vhi, g_vhi);
    cudaGetSymbolAddress((void**)&ahi, g_ahi);

    cudaFuncSetAttribute(gemm_qkv, cudaFuncAttributeMaxDynamicSharedMemorySize, GEMM2T_SMEM);
    cudaFuncSetAttribute(gemm_out, cudaFuncAttributeMaxDynamicSharedMemorySize, GEMM1T_SMEM);
    cudaFuncSetAttribute(attn_mma, cudaFuncAttributeMaxDynamicSharedMemorySize, ATT_SMEM);

    // fused hi/lo splits (x) + hi conversions (weights)
    {
        int n4 = N4_X + N4_WQ + N4_WO;
        split_all<<<(n4 + 255) / 256, 256>>>(x, xhi, xlo, Wqkv, wqh, Wo, woh);
    }

    // 1) qkv projection -> fp16 Q(hi/lo, scaled), K(hi), V(hi)
    {
        dim3 grid(3 * DIM / BN, NTOK / BM);   // (24, 32)
        gemm_qkv<<<grid, 128, GEMM2T_SMEM>>>(xhi, xlo, wqh, qhi, qlo, khi, vhi);
    }

    // 2) tensor-core flash attention (fp16 in, fp16 hi out)
    {
        dim3 grid(SEQ / 128, BATCH * HEADS);   // (16, 32)
        attn_mma<<<grid, 256, ATT_SMEM>>>(qhi, qlo, khi, vhi, ahi);
    }

    // 3) out = attn_hi @ Wo^T (1-term, fp32 out)
    {
        dim3 grid(DIM / BN, NTOK / BM);        // (8, 32)
        gemm_out<<<grid, 128, GEMM1T_SMEM>>>(ahi, woh, out);
    }
}

// round 13
// speedup vs baseline: 1.6235x; 1.2750x over previous
#include <cuda_runtime.h>
#include <cuda_fp16.h>
#include <cstdint>

// Problem constants
#define BATCH 2
#define SEQ   2048
#define DIM   1024
#define HEADS 16
#define HD    64
#define NTOK  (BATCH*SEQ)   // 4096

// ---------------------------------------------------------------------------
// Scratch (__device__ globals; allocation-free rule)
// ---------------------------------------------------------------------------
__device__ __half g_xhi[(size_t)NTOK * DIM];
__device__ __half g_wqh[(size_t)3 * DIM * DIM];     // weights: hi only
__device__ __half g_woh[(size_t)DIM * DIM];
__device__ __half g_qhi[(size_t)NTOK * DIM];        // Q (pre-scaled) hi
__device__ __half g_khi[(size_t)NTOK * DIM];        // K hi
__device__ __half g_vhi[(size_t)NTOK * DIM];        // V hi
__device__ __half g_ahi[(size_t)NTOK * DIM];        // attn out hi

// ---------------------------------------------------------------------------
// PTX helpers (baseline sm_100-safe)
// ---------------------------------------------------------------------------
__device__ __forceinline__ uint32_t smem_u32(const void* p) {
    uint32_t a;
    asm("{ .reg .u64 t; cvta.to.shared.u64 t, %1; cvt.u32.u64 %0, t; }" : "=r"(a) : "l"(p));
    return a;
}
#define SWZ64(off)  ((off) ^ (((off) >> 3) & 0x30))
#define SWZ128(off) ((off) ^ (((off) >> 3) & 0x70))

#define CP_ASYNC16(saddr, gptr) \
    asm volatile("cp.async.cg.shared.global [%0], [%1], 16;\n" :: "r"(saddr), "l"(gptr))
#define CP_COMMIT() asm volatile("cp.async.commit_group;\n" ::: "memory")
#define CP_WAIT(N)  asm volatile("cp.async.wait_group %0;\n" :: "n"(N) : "memory")

#define LDSM_X4(r0, r1, r2, r3, addr) \
    asm volatile("ldmatrix.sync.aligned.m8n8.x4.shared.b16 {%0,%1,%2,%3}, [%4];" \
                 : "=r"(r0), "=r"(r1), "=r"(r2), "=r"(r3) : "r"(addr))
#define LDSM_X4_T(r0, r1, r2, r3, addr) \
    asm volatile("ldmatrix.sync.aligned.m8n8.x4.trans.shared.b16 {%0,%1,%2,%3}, [%4];" \
                 : "=r"(r0), "=r"(r1), "=r"(r2), "=r"(r3) : "r"(addr))

#define MMAF16(c, a, b0, b1) \
    asm volatile("mma.sync.aligned.m16n8k16.row.col.f32.f16.f16.f32 " \
                 "{%0,%1,%2,%3}, {%4,%5,%6,%7}, {%8,%9}, {%0,%1,%2,%3};" \
                 : "+f"((c)[0]), "+f"((c)[1]), "+f"((c)[2]), "+f"((c)[3]) \
                 : "r"((a)[0]), "r"((a)[1]), "r"((a)[2]), "r"((a)[3]), \
                   "r"(b0), "r"(b1))

__device__ __forceinline__ uint32_t pack_h2(float a, float b) {
    __half2 v(__float2half(a), __float2half(b));
    return *(uint32_t*)&v;
}

// ---------------------------------------------------------------------------
// fused convert kernel: x, Wqkv, Wo -> fp16 hi
// ---------------------------------------------------------------------------
#define N4_X  (NTOK * DIM / 4)
#define N4_WQ (3 * DIM * DIM / 4)
#define N4_WO (DIM * DIM / 4)

__global__ void split_all(const float* __restrict__ x,  __half* __restrict__ xhi,
                          const float* __restrict__ wq, __half* __restrict__ wqh,
                          const float* __restrict__ wo, __half* __restrict__ woh)
{
    int i = blockIdx.x * blockDim.x + threadIdx.x;
    const float* src; __half* dst;
    if (i < N4_X) { src = x; dst = xhi; }
    else if (i < N4_X + N4_WQ) { i -= N4_X; src = wq; dst = wqh; }
    else if (i < N4_X + N4_WQ + N4_WO) { i -= N4_X + N4_WQ; src = wo; dst = woh; }
    else return;
    float4 v = ((const float4*)src)[i];
    __half2* hp = (__half2*)(dst + (size_t)i * 4);
    hp[0] = __half2(__float2half(v.x), __float2half(v.y));
    hp[1] = __half2(__float2half(v.z), __float2half(v.w));
}

// ---------------------------------------------------------------------------
// GEMM common tile constants (1-term everywhere now)
// ---------------------------------------------------------------------------
#define BM 128
#define BN 128
#define BK 32
#define A_BYTES (BM * BK * 2)              // 8192
#define B_BYTES (BN * BK * 2)              // 8192
#define STAGE1_B (A_BYTES + B_BYTES)       // 16384
#define GEMM1T_SMEM (3 * STAGE1_B)         // 49152

// Shared 1-term mainloop: leaves accumulators in c[4][8][4]
#define GEMM_MAINLOOP_1T(Ahi, Bh, K)                                                \
    extern __shared__ __align__(1024) char smem[];                                  \
    const uint32_t sbase = smem_u32(smem);                                          \
    const int tid  = threadIdx.x;                                                   \
    const int wid  = tid >> 5;                                                      \
    const int lane = tid & 31;                                                      \
    const int m0 = blockIdx.y * BM;                                                 \
    const int n0 = blockIdx.x * BN;                                                 \
    const int m_off = (wid & 1) * 64;                                               \
    const int n_off = (wid >> 1) * 64;                                              \
    const __half* aSrc = Ahi + (size_t)m0 * K;                                      \
    const __half* bSrc = Bh + (size_t)n0 * K;                                       \
    const int NIT = K / BK;                                                         \
    auto load_stage = [&](int sbuf, int k0) {                                       \
        uint32_t stg = sbase + sbuf * STAGE1_B;                                     \
        _Pragma("unroll")                                                           \
        for (int r = 0; r < 4; r++) {                                               \
            int idx = r * 128 + tid;                                                \
            int row = idx >> 2, cch = idx & 3;                                      \
            uint32_t soff = SWZ64((uint32_t)(row * 64 + cch * 16));                 \
            CP_ASYNC16(stg + soff, aSrc + k0 + (size_t)row * K + cch * 8);          \
        }                                                                           \
        _Pragma("unroll")                                                           \
        for (int r = 0; r < 4; r++) {                                               \
            int idx = r * 128 + tid;                                                \
            int row = idx >> 2, cch = idx & 3;                                      \
            uint32_t soff = SWZ64((uint32_t)(row * 64 + cch * 16));                 \
            CP_ASYNC16(stg + A_BYTES + soff, bSrc + k0 + (size_t)row * K + cch * 8);\
        }                                                                           \
    };                                                                              \
    float c[4][8][4];                                                               \
    _Pragma("unroll")                                                               \
    for (int i = 0; i < 4; i++)                                                     \
        _Pragma("unroll")                                                           \
        for (int j = 0; j < 8; j++)                                                 \
            _Pragma("unroll")                                                       \
            for (int t = 0; t < 4; t++) c[i][j][t] = 0.f;                           \
    load_stage(0, 0); CP_COMMIT();                                                  \
    load_stage(1, BK); CP_COMMIT();                                                 \
    const int lr = lane & 15;                                                       \
    const int lk = lane >> 4;                                                       \
    int sbuf = 0;                                                                   \
    for (int it = 0; it < NIT; it++) {                                              \
        CP_WAIT(1);                                                                 \
        __syncthreads();                                                            \
        if (it + 2 < NIT) { load_stage((sbuf + 2) % 3, (it + 2) * BK); CP_COMMIT(); } \
        uint32_t stg  = sbase + sbuf * STAGE1_B;                                    \
        uint32_t aHiB = stg;                                                        \
        uint32_t bHiB = stg + A_BYTES;                                              \
        _Pragma("unroll")                                                           \
        for (int ks = 0; ks < 2; ks++) {                                            \
            uint32_t ahi[4][4];                                                     \
            _Pragma("unroll")                                                       \
            for (int mi = 0; mi < 4; mi++) {                                        \
                uint32_t sw = SWZ64((uint32_t)((m_off + mi * 16 + lr) * 64 + ks * 32 + lk * 16)); \
                LDSM_X4(ahi[mi][0], ahi[mi][1], ahi[mi][2], ahi[mi][3], aHiB + sw); \
            }                                                                       \
            _Pragma("unroll")                                                       \
            for (int ng = 0; ng < 4; ng++) {                                        \
                uint32_t sw = SWZ64((uint32_t)((n_off + ng * 16 + lr) * 64 + ks * 32 + lk * 16)); \
                uint32_t bh0, bh1, bh2, bh3;                                        \
                LDSM_X4(bh0, bh1, bh2, bh3, bHiB + sw);                             \
                _Pragma("unroll")                                                   \
                for (int mi = 0; mi < 4; mi++) {                                    \
                    MMAF16(c[mi][ng*2+0], ahi[mi], bh0, bh2);                       \
                    MMAF16(c[mi][ng*2+1], ahi[mi], bh1, bh3);                       \
                }                                                                   \
            }                                                                       \
        }                                                                           \
        sbuf = (sbuf + 1) % 3;                                                      \
    }                                                                               \
    const int cr = lane >> 2;                                                       \
    const int cc = (lane & 3) * 2;

// ---------------------------------------------------------------------------
// GEMM1: qkv projection (1-term), epilogue -> Q(hi, scaled), K(hi), V(hi)
// ---------------------------------------------------------------------------
__global__ __launch_bounds__(128, 2)
void gemm_qkv(const __half* __restrict__ Ahi, const __half* __restrict__ Bh,
              __half* __restrict__ qhi, __half* __restrict__ khi,
              __half* __restrict__ vhi)
{
    GEMM_MAINLOOP_1T(Ahi, Bh, DIM)

    const int seg  = n0 >> 10;           // 0=Q, 1=K, 2=V
    const int col0 = (n0 & 1023) + n_off;
    __half* dst = (seg == 0) ? qhi : (seg == 1) ? khi : vhi;
    const float sc = (seg == 0) ? 0.125f : 1.0f;
#pragma unroll
    for (int mi = 0; mi < 4; mi++) {
        int r0 = m0 + m_off + mi * 16 + cr;
#pragma unroll
        for (int j = 0; j < 8; j++) {
            int col = col0 + j * 8 + cc;
            size_t off0 = (size_t)r0 * DIM + col;
            size_t off1 = (size_t)(r0 + 8) * DIM + col;
            *(uint32_t*)(dst + off0) = pack_h2(c[mi][j][0] * sc, c[mi][j][1] * sc);
            *(uint32_t*)(dst + off1) = pack_h2(c[mi][j][2] * sc, c[mi][j][3] * sc);
        }
    }
}

// ---------------------------------------------------------------------------
// GEMM2: out projection (1-term), fp32 out
// ---------------------------------------------------------------------------
__global__ __launch_bounds__(128, 2)
void gemm_out(const __half* __restrict__ Ahi, const __half* __restrict__ Bh,
              float* __restrict__ C)
{
    GEMM_MAINLOOP_1T(Ahi, Bh, DIM)

#pragma unroll
    for (int mi = 0; mi < 4; mi++) {
        int r0 = m0 + m_off + mi * 16 + cr;
#pragma unroll
        for (int j = 0; j < 8; j++) {
            int col = n0 + n_off + j * 8 + cc;
            *(float2*)(C + (size_t)r0 * DIM + col)       = make_float2(c[mi][j][0], c[mi][j][1]);
            *(float2*)(C + (size_t)(r0 + 8) * DIM + col) = make_float2(c[mi][j][2], c[mi][j][3]);
        }
    }
}

// ---------------------------------------------------------------------------
// Tensor-core flash attention: S = Qhi·Khi (1-term); PV 1-term (P hi).
// ALiBi + causal. fp16 in; fp16 hi out.
// smem: Q_HI 0 (16384), stages at 16384 (Khi+Vhi 16384) x2, P_HI 49152
//       -> 65536 total; 2 CTAs/SM.
// ---------------------------------------------------------------------------
#define ATT_SMEM 65536
#define Q_HI 0
#define STG0 16384
#define P_HI 49152

__global__ __launch_bounds__(256, 2)
void attn_mma(const __half* __restrict__ qhi,
              const __half* __restrict__ khi, const __half* __restrict__ vhi,
              __half* __restrict__ out_hi)
{
    extern __shared__ __align__(1024) char smem[];
    const uint32_t sbase = smem_u32(smem);
    const int tid  = threadIdx.x;
    const int wid  = tid >> 5;
    const int lane = tid & 31;
    const int lr   = lane & 15;
    const int lk   = lane >> 4;

    const int qt = (int)(gridDim.x - 1 - blockIdx.x);   // largest tiles first
    const int bh = blockIdx.y;
    const int b  = bh >> 4;
    const int h  = bh & 15;
    const int q0 = qt * 128;

    const float slope = exp2f(-0.5f * (float)(h + 1));

    const __half* qh_base = qhi + (size_t)(b * SEQ) * DIM + h * HD;
    const __half* kh_base = khi + (size_t)(b * SEQ) * DIM + h * HD;
    const __half* vh_base = vhi + (size_t)(b * SEQ) * DIM + h * HD;

    // ---- issue Q tile loads (128 rows x 128 B) ----
#pragma unroll
    for (int r = 0; r < 4; r++) {
        int idx = r * 256 + tid;
        int row = idx >> 3;
        int ch  = idx & 7;
        uint32_t soff = SWZ128((uint32_t)(row * 128 + ch * 16));
        CP_ASYNC16(sbase + Q_HI + soff, qh_base + (size_t)(q0 + row) * DIM + ch * 8);
    }

    const int nkt = 2 * qt + 2;

    auto issue_kv = [&](int kt, int s) {
        uint32_t stg = sbase + STG0 + s * 16384;
        int k0 = kt * 64;
#pragma unroll
        for (int r = 0; r < 2; r++) {
            int idx = r * 256 + tid;
            int row = idx >> 3;
            int ch  = idx & 7;
            uint32_t soff = SWZ128((uint32_t)(row * 128 + ch * 16));
            CP_ASYNC16(stg + soff,        kh_base + (size_t)(k0 + row) * DIM + ch * 8);
            CP_ASYNC16(stg + 8192 + soff, vh_base + (size_t)(k0 + row) * DIM + ch * 8);
        }
    };

    issue_kv(0, 0);
    CP_COMMIT();

    float cs[8][4];
    float co[8][4];
#pragma unroll
    for (int j = 0; j < 8; j++)
#pragma unroll
        for (int t = 0; t < 4; t++) co[j][t] = 0.f;

    float m0v = -1e30f, m1v = -1e30f, l0v = 0.f, l1v = 0.f;

    const int r0 = lane >> 2;
    const int ccol = (lane & 3) * 2;
    const int gi0 = q0 + wid * 16 + r0;
    const int gi1 = gi0 + 8;

    for (int kt = 0; kt < nkt; kt++) {
        const int s = kt & 1;
        const int k0 = kt * 64;
        const uint32_t stgo = STG0 + s * 16384;

        __syncthreads();
        if (kt + 1 < nkt) {
            issue_kv(kt + 1, s ^ 1);
            CP_COMMIT();
            CP_WAIT(1);
        } else {
            CP_WAIT(0);
        }
        __syncthreads();

        // ---- S = Q K^T (1-term) ----
#pragma unroll
        for (int j = 0; j < 8; j++)
#pragma unroll
            for (int t = 0; t < 4; t++) cs[j][t] = 0.f;

        uint32_t kHiB = sbase + stgo;
#pragma unroll
        for (int ks = 0; ks < 4; ks++) {
            uint32_t qoff = SWZ128((uint32_t)((wid * 16 + lr) * 128 + ks * 32 + lk * 16));
            uint32_t ahi[4];
            LDSM_X4(ahi[0], ahi[1], ahi[2], ahi[3], sbase + Q_HI + qoff);
#pragma unroll
            for (int ng = 0; ng < 4; ng++) {
                uint32_t boff = SWZ128((uint32_t)((ng * 16 + lr) * 128 + ks * 32 + lk * 16));
                uint32_t bh0, bh1, bh2, bh3;
                LDSM_X4(bh0, bh1, bh2, bh3, kHiB + boff);
                MMAF16(cs[ng*2+0], ahi, bh0, bh2);
                MMAF16(cs[ng*2+1], ahi, bh1, bh3);
            }
        }

        // ---- ALiBi + causal mask ----
#pragma unroll
        for (int nb = 0; nb < 8; nb++) {
#pragma unroll
            for (int cidx = 0; cidx < 2; cidx++) {
                int gj = k0 + nb * 8 + ccol + cidx;
                float rel0 = slope * (float)(gj - gi0);
                float rel1 = slope * (float)(gj - gi1);
                cs[nb][cidx]     = (gj > gi0) ? -1e30f : cs[nb][cidx]     - rel0;
                cs[nb][2 + cidx] = (gj > gi1) ? -1e30f : cs[nb][2 + cidx] - rel1;
            }
        }

        // ---- online softmax ----
        float mx0 = -1e30f, mx1 = -1e30f;
#pragma unroll
        for (int nb = 0; nb < 8; nb++) {
            mx0 = fmaxf(mx0, fmaxf(cs[nb][0], cs[nb][1]));
            mx1 = fmaxf(mx1, fmaxf(cs[nb][2], cs[nb][3]));
        }
        mx0 = fmaxf(mx0, __shfl_xor_sync(0xffffffff, mx0, 1));
        mx0 = fmaxf(mx0, __shfl_xor_sync(0xffffffff, mx0, 2));
        mx1 = fmaxf(mx1, __shfl_xor_sync(0xffffffff, mx1, 1));
        mx1 = fmaxf(mx1, __shfl_xor_sync(0xffffffff, mx1, 2));

        float mn0 = fmaxf(m0v, mx0), mn1 = fmaxf(m1v, mx1);
        float corr0 = __expf(m0v - mn0), corr1 = __expf(m1v - mn1);
        m0v = mn0; m1v = mn1;

        float sum0 = 0.f, sum1 = 0.f;
        const int prow0 = wid * 16 + r0;
#pragma unroll
        for (int nb = 0; nb < 8; nb++) {
            float p00 = __expf(cs[nb][0] - mn0);
            float p01 = __expf(cs[nb][1] - mn0);
            float p10 = __expf(cs[nb][2] - mn1);
            float p11 = __expf(cs[nb][3] - mn1);
            sum0 += p00 + p01;
            sum1 += p10 + p11;
            uint32_t off0 = SWZ128((uint32_t)(prow0 * 128 + nb * 16 + (lane & 3) * 4));
            uint32_t off1 = SWZ128((uint32_t)((prow0 + 8) * 128 + nb * 16 + (lane & 3) * 4));
            *(uint32_t*)(smem + P_HI + off0) = pack_h2(p00, p01);
            *(uint32_t*)(smem + P_HI + off1) = pack_h2(p10, p11);
        }
        sum0 += __shfl_xor_sync(0xffffffff, sum0, 1);
        sum0 += __shfl_xor_sync(0xffffffff, sum0, 2);
        sum1 += __shfl_xor_sync(0xffffffff, sum1, 1);
        sum1 += __shfl_xor_sync(0xffffffff, sum1, 2);
        l0v = l0v * corr0 + sum0;
        l1v = l1v * corr1 + sum1;

#pragma unroll
        for (int nb = 0; nb < 8; nb++) {
            co[nb][0] *= corr0; co[nb][1] *= corr0;
            co[nb][2] *= corr1; co[nb][3] *= corr1;
        }
        __syncwarp();

        // ---- O += P V (1-term; V via ldmatrix.trans) ----
        uint32_t vHiB = sbase + stgo + 8192;
#pragma unroll
        for (int ks = 0; ks < 4; ks++) {
            uint32_t poff = SWZ128((uint32_t)((wid * 16 + lr) * 128 + ks * 32 + lk * 16));
            uint32_t phi[4];
            LDSM_X4(phi[0], phi[1], phi[2], phi[3], sbase + P_HI + poff);
#pragma unroll
            for (int ng = 0; ng < 4; ng++) {
                uint32_t voff = SWZ128((uint32_t)((ks * 16 + lr) * 128 + ng * 32 + lk * 16));
                uint32_t vh0, vh1, vh2, vh3;
                LDSM_X4_T(vh0, vh1, vh2, vh3, vHiB + voff);
                MMAF16(co[ng*2+0], phi, vh0, vh1);
                MMAF16(co[ng*2+1], phi, vh2, vh3);
            }
        }
    }

    // ---- normalize + write fp16 hi ----
    float inv0 = 1.0f / l0v, inv1 = 1.0f / l1v;
    size_t row0 = (size_t)(b * SEQ + gi0) * DIM + h * HD;
    size_t row1 = (size_t)(b * SEQ + gi1) * DIM + h * HD;
#pragma unroll
    for (int nb = 0; nb < 8; nb++) {
        int d = nb * 8 + ccol;
        *(uint32_t*)(out_hi + row0 + d) = pack_h2(co[nb][0] * inv0, co[nb][1] * inv0);
        *(uint32_t*)(out_hi + row1 + d) = pack_h2(co[nb][2] * inv1, co[nb][3] * inv1);
    }
}

// ---------------------------------------------------------------------------
extern "C" void kernel_launch(void* const* d_in, const int* in_sizes, int n_in,
                              void* d_out, int out_size)
{
    const float* x    = (const float*)d_in[0];
    const float* Wqkv = (const float*)d_in[1];
    const float* Wo   = (const float*)d_in[2];
    float* out = (float*)d_out;

    __half *xhi, *wqh, *woh, *qhi, *khi, *vhi, *ahi;
    cudaGetSymbolAddress((void**)&xhi, g_xhi);
    cudaGetSymbolAddress((void**)&wqh, g_wqh);
    cudaGetSymbolAddress((void**)&woh, g_woh);
    cudaGetSymbolAddress((void**)&qhi, g_qhi);
    cudaGetSymbolAddress((void**)&khi, g_khi);
    cudaGetSymbolAddress((void**)&vhi, g_vhi);
    cudaGetSymbolAddress((void**)&ahi, g_ahi);

    cudaFuncSetAttribute(gemm_qkv, cudaFuncAttributeMaxDynamicSharedMemorySize, GEMM1T_SMEM);
    cudaFuncSetAttribute(gemm_out, cudaFuncAttributeMaxDynamicSharedMemorySize, GEMM1T_SMEM);
    cudaFuncSetAttribute(attn_mma, cudaFuncAttributeMaxDynamicSharedMemorySize, ATT_SMEM);

    // fused fp16 conversions (x + weights)
    {
        int n4 = N4_X + N4_WQ + N4_WO;
        split_all<<<(n4 + 255) / 256, 256>>>(x, xhi, Wqkv, wqh, Wo, woh);
    }

    // 1) qkv projection -> fp16 Q(hi, scaled), K(hi), V(hi)
    {
        dim3 grid(3 * DIM / BN, NTOK / BM);   // (24, 32)
        gemm_qkv<<<grid, 128, GEMM1T_SMEM>>>(xhi, wqh, qhi, khi, vhi);
    }

    // 2) tensor-core flash attention (fp16 in, fp16 hi out)
    {
        dim3 grid(SEQ / 128, BATCH * HEADS);   // (16, 32)
        attn_mma<<<grid, 256, ATT_SMEM>>>(qhi, khi, vhi, ahi);
    }

    // 3) out = attn_hi @ Wo^T (1-term, fp32 out)
    {
        dim3 grid(DIM / BN, NTOK / BM);        // (8, 32)
        gemm_out<<<grid, 128, GEMM1T_SMEM>>>(ahi, woh, out);
    }
}

// round 14
// speedup vs baseline: 1.7288x; 1.0649x over previous
#include <cuda_runtime.h>
#include <cuda_fp16.h>
#include <cstdint>

// Problem constants
#define BATCH 2
#define SEQ   2048
#define DIM   1024
#define HEADS 16
#define HD    64
#define NTOK  (BATCH*SEQ)   // 4096

// ---------------------------------------------------------------------------
// Scratch (__device__ globals; allocation-free rule)
// ---------------------------------------------------------------------------
__device__ __half g_xhi[(size_t)NTOK * DIM];
__device__ __half g_wqh[(size_t)3 * DIM * DIM];
__device__ __half g_woh[(size_t)DIM * DIM];
__device__ __half g_qhi[(size_t)NTOK * DIM];        // Q (pre-scaled) hi
__device__ __half g_khi[(size_t)NTOK * DIM];        // K hi
__device__ __half g_vhi[(size_t)NTOK * DIM];        // V hi
__device__ __half g_ahi[(size_t)NTOK * DIM];        // attn out hi

// ---------------------------------------------------------------------------
// PTX helpers (baseline sm_100-safe)
// ---------------------------------------------------------------------------
__device__ __forceinline__ uint32_t smem_u32(const void* p) {
    uint32_t a;
    asm("{ .reg .u64 t; cvta.to.shared.u64 t, %1; cvt.u32.u64 %0, t; }" : "=r"(a) : "l"(p));
    return a;
}
#define SWZ128(off) ((off) ^ (((off) >> 3) & 0x70))

#define CP_ASYNC16(saddr, gptr) \
    asm volatile("cp.async.cg.shared.global [%0], [%1], 16;\n" :: "r"(saddr), "l"(gptr))
#define CP_COMMIT() asm volatile("cp.async.commit_group;\n" ::: "memory")
#define CP_WAIT(N)  asm volatile("cp.async.wait_group %0;\n" :: "n"(N) : "memory")

#define LDSM_X4(r0, r1, r2, r3, addr) \
    asm volatile("ldmatrix.sync.aligned.m8n8.x4.shared.b16 {%0,%1,%2,%3}, [%4];" \
                 : "=r"(r0), "=r"(r1), "=r"(r2), "=r"(r3) : "r"(addr))
#define LDSM_X4_T(r0, r1, r2, r3, addr) \
    asm volatile("ldmatrix.sync.aligned.m8n8.x4.trans.shared.b16 {%0,%1,%2,%3}, [%4];" \
                 : "=r"(r0), "=r"(r1), "=r"(r2), "=r"(r3) : "r"(addr))

#define MMAF16(c, a, b0, b1) \
    asm volatile("mma.sync.aligned.m16n8k16.row.col.f32.f16.f16.f32 " \
                 "{%0,%1,%2,%3}, {%4,%5,%6,%7}, {%8,%9}, {%0,%1,%2,%3};" \
                 : "+f"((c)[0]), "+f"((c)[1]), "+f"((c)[2]), "+f"((c)[3]) \
                 : "r"((a)[0]), "r"((a)[1]), "r"((a)[2]), "r"((a)[3]), \
                   "r"(b0), "r"(b1))

__device__ __forceinline__ uint32_t pack_h2(float a, float b) {
    __half2 v(__float2half(a), __float2half(b));
    return *(uint32_t*)&v;
}

// ---------------------------------------------------------------------------
// fused convert kernel: x, Wqkv, Wo -> fp16
// ---------------------------------------------------------------------------
#define N4_X  (NTOK * DIM / 4)
#define N4_WQ (3 * DIM * DIM / 4)
#define N4_WO (DIM * DIM / 4)

__global__ void split_all(const float* __restrict__ x,  __half* __restrict__ xhi,
                          const float* __restrict__ wq, __half* __restrict__ wqh,
                          const float* __restrict__ wo, __half* __restrict__ woh)
{
    int i = blockIdx.x * blockDim.x + threadIdx.x;
    const float* src; __half* dst;
    if (i < N4_X) { src = x; dst = xhi; }
    else if (i < N4_X + N4_WQ) { i -= N4_X; src = wq; dst = wqh; }
    else if (i < N4_X + N4_WQ + N4_WO) { i -= N4_X + N4_WQ; src = wo; dst = woh; }
    else return;
    float4 v = ((const float4*)src)[i];
    __half2* hp = (__half2*)(dst + (size_t)i * 4);
    hp[0] = __half2(__float2half(v.x), __float2half(v.y));
    hp[1] = __half2(__float2half(v.z), __float2half(v.w));
}

// ---------------------------------------------------------------------------
// 1-term fp16 GEMM: CTA 128x128, 128 threads (4 warps x 64x64), BK=64, 3 stages.
// One __syncthreads per k-iteration (canonical multi-stage pattern).
// ---------------------------------------------------------------------------
#define BM 128
#define BN 128
#define BKG 64
#define AG_BYTES (BM * BKG * 2)            // 16384
#define BG_BYTES (BN * BKG * 2)            // 16384
#define STAGE_B (AG_BYTES + BG_BYTES)      // 32768
#define GEMM_SMEM (3 * STAGE_B)            // 98304

#define GEMM_MAINLOOP_1T(Ahi, Bh, K)                                                \
    extern __shared__ __align__(1024) char smem[];                                  \
    const uint32_t sbase = smem_u32(smem);                                          \
    const int tid  = threadIdx.x;                                                   \
    const int wid  = tid >> 5;                                                      \
    const int lane = tid & 31;                                                      \
    const int m0 = blockIdx.y * BM;                                                 \
    const int n0 = blockIdx.x * BN;                                                 \
    const int m_off = (wid & 1) * 64;                                               \
    const int n_off = (wid >> 1) * 64;                                              \
    const __half* aSrc = Ahi + (size_t)m0 * K;                                      \
    const __half* bSrc = Bh + (size_t)n0 * K;                                       \
    const int NIT = K / BKG;                                                        \
    auto load_stage = [&](int sbuf, int k0) {                                       \
        uint32_t stg = sbase + sbuf * STAGE_B;                                      \
        _Pragma("unroll")                                                           \
        for (int r = 0; r < 8; r++) {                                               \
            int idx = r * 128 + tid;                                                \
            int row = idx >> 3, cch = idx & 7;                                      \
            uint32_t soff = SWZ128((uint32_t)(row * 128 + cch * 16));               \
            CP_ASYNC16(stg + soff, aSrc + k0 + (size_t)row * K + cch * 8);          \
        }                                                                           \
        _Pragma("unroll")                                                           \
        for (int r = 0; r < 8; r++) {                                               \
            int idx = r * 128 + tid;                                                \
            int row = idx >> 3, cch = idx & 7;                                      \
            uint32_t soff = SWZ128((uint32_t)(row * 128 + cch * 16));               \
            CP_ASYNC16(stg + AG_BYTES + soff, bSrc + k0 + (size_t)row * K + cch * 8);\
        }                                                                           \
    };                                                                              \
    float c[4][8][4];                                                               \
    _Pragma("unroll")                                                               \
    for (int i = 0; i < 4; i++)                                                     \
        _Pragma("unroll")                                                           \
        for (int j = 0; j < 8; j++)                                                 \
            _Pragma("unroll")                                                       \
            for (int t = 0; t < 4; t++) c[i][j][t] = 0.f;                           \
    load_stage(0, 0); CP_COMMIT();                                                  \
    load_stage(1, BKG); CP_COMMIT();                                                \
    const int lr = lane & 15;                                                       \
    const int lk = lane >> 4;                                                       \
    int sbuf = 0;                                                                   \
    for (int it = 0; it < NIT; it++) {                                              \
        if (it + 1 < NIT) { CP_WAIT(1); } else { CP_WAIT(0); }                      \
        __syncthreads();                                                            \
        if (it + 2 < NIT) { load_stage((sbuf + 2) % 3, (it + 2) * BKG); CP_COMMIT(); } \
        uint32_t stg  = sbase + sbuf * STAGE_B;                                     \
        uint32_t aHiB = stg;                                                        \
        uint32_t bHiB = stg + AG_BYTES;                                             \
        _Pragma("unroll")                                                           \
        for (int ks = 0; ks < 4; ks++) {                                            \
            uint32_t ahi[4][4];                                                     \
            _Pragma("unroll")                                                       \
            for (int mi = 0; mi < 4; mi++) {                                        \
                uint32_t sw = SWZ128((uint32_t)((m_off + mi * 16 + lr) * 128 + ks * 32 + lk * 16)); \
                LDSM_X4(ahi[mi][0], ahi[mi][1], ahi[mi][2], ahi[mi][3], aHiB + sw); \
            }                                                                       \
            _Pragma("unroll")                                                       \
            for (int ng = 0; ng < 4; ng++) {                                        \
                uint32_t sw = SWZ128((uint32_t)((n_off + ng * 16 + lr) * 128 + ks * 32 + lk * 16)); \
                uint32_t bh0, bh1, bh2, bh3;                                        \
                LDSM_X4(bh0, bh1, bh2, bh3, bHiB + sw);                             \
                _Pragma("unroll")                                                   \
                for (int mi = 0; mi < 4; mi++) {                                    \
                    MMAF16(c[mi][ng*2+0], ahi[mi], bh0, bh2);                       \
                    MMAF16(c[mi][ng*2+1], ahi[mi], bh1, bh3);                       \
                }                                                                   \
            }                                                                       \
        }                                                                           \
        sbuf = (sbuf + 1) % 3;                                                      \
    }                                                                               \
    const int cr = lane >> 2;                                                       \
    const int cc = (lane & 3) * 2;

// ---------------------------------------------------------------------------
// GEMM1: qkv projection, epilogue -> Q(hi, scaled), K(hi), V(hi)
// ---------------------------------------------------------------------------
__global__ __launch_bounds__(128, 2)
void gemm_qkv(const __half* __restrict__ Ahi, const __half* __restrict__ Bh,
              __half* __restrict__ qhi, __half* __restrict__ khi,
              __half* __restrict__ vhi)
{
    GEMM_MAINLOOP_1T(Ahi, Bh, DIM)

    const int seg  = n0 >> 10;           // 0=Q, 1=K, 2=V
    const int col0 = (n0 & 1023) + n_off;
    __half* dst = (seg == 0) ? qhi : (seg == 1) ? khi : vhi;
    const float sc = (seg == 0) ? 0.125f : 1.0f;
#pragma unroll
    for (int mi = 0; mi < 4; mi++) {
        int r0 = m0 + m_off + mi * 16 + cr;
#pragma unroll
        for (int j = 0; j < 8; j++) {
            int col = col0 + j * 8 + cc;
            *(uint32_t*)(dst + (size_t)r0 * DIM + col) =
                pack_h2(c[mi][j][0] * sc, c[mi][j][1] * sc);
            *(uint32_t*)(dst + (size_t)(r0 + 8) * DIM + col) =
                pack_h2(c[mi][j][2] * sc, c[mi][j][3] * sc);
        }
    }
}

// ---------------------------------------------------------------------------
// GEMM2: out projection, fp32 out
// ---------------------------------------------------------------------------
__global__ __launch_bounds__(128, 2)
void gemm_out(const __half* __restrict__ Ahi, const __half* __restrict__ Bh,
              float* __restrict__ C)
{
    GEMM_MAINLOOP_1T(Ahi, Bh, DIM)

#pragma unroll
    for (int mi = 0; mi < 4; mi++) {
        int r0 = m0 + m_off + mi * 16 + cr;
#pragma unroll
        for (int j = 0; j < 8; j++) {
            int col = n0 + n_off + j * 8 + cc;
            *(float2*)(C + (size_t)r0 * DIM + col)       = make_float2(c[mi][j][0], c[mi][j][1]);
            *(float2*)(C + (size_t)(r0 + 8) * DIM + col) = make_float2(c[mi][j][2], c[mi][j][3]);
        }
    }
}

// ---------------------------------------------------------------------------
// Flash attention: S = Qhi·Khi; PV = Phi·Vhi. ALiBi + causal.
// 3-stage K/V cp.async pipeline, ONE __syncthreads per key-tile.
// Fully-masked warps skip the diagonal tile's compute.
// smem: Q 16384, KV stages 16384x3 at 16384, P 16384 at 65536 -> 81920.
// ---------------------------------------------------------------------------
#define ATT_SMEM 81920
#define Q_HI 0
#define STG0 16384
#define P_HI 65536

__global__ __launch_bounds__(256, 2)
void attn_mma(const __half* __restrict__ qhi,
              const __half* __restrict__ khi, const __half* __restrict__ vhi,
              __half* __restrict__ out_hi)
{
    extern __shared__ __align__(1024) char smem[];
    const uint32_t sbase = smem_u32(smem);
    const int tid  = threadIdx.x;
    const int wid  = tid >> 5;
    const int lane = tid & 31;
    const int lr   = lane & 15;
    const int lk   = lane >> 4;

    const int qt = (int)(gridDim.x - 1 - blockIdx.x);   // largest tiles first
    const int bh = blockIdx.y;
    const int b  = bh >> 4;
    const int h  = bh & 15;
    const int q0 = qt * 128;

    const float slope = exp2f(-0.5f * (float)(h + 1));

    const __half* qh_base = qhi + (size_t)(b * SEQ) * DIM + h * HD;
    const __half* kh_base = khi + (size_t)(b * SEQ) * DIM + h * HD;
    const __half* vh_base = vhi + (size_t)(b * SEQ) * DIM + h * HD;

    // ---- issue Q tile loads (group 0, with KV tile 0) ----
#pragma unroll
    for (int r = 0; r < 4; r++) {
        int idx = r * 256 + tid;
        int row = idx >> 3;
        int ch  = idx & 7;
        uint32_t soff = SWZ128((uint32_t)(row * 128 + ch * 16));
        CP_ASYNC16(sbase + Q_HI + soff, qh_base + (size_t)(q0 + row) * DIM + ch * 8);
    }

    const int nkt = 2 * qt + 2;

    auto issue_kv = [&](int kt, int s) {
        uint32_t stg = sbase + STG0 + s * 16384;
        int k0 = kt * 64;
#pragma unroll
        for (int r = 0; r < 2; r++) {
            int idx = r * 256 + tid;
            int row = idx >> 3;
            int ch  = idx & 7;
            uint32_t soff = SWZ128((uint32_t)(row * 128 + ch * 16));
            CP_ASYNC16(stg + soff,        kh_base + (size_t)(k0 + row) * DIM + ch * 8);
            CP_ASYNC16(stg + 8192 + soff, vh_base + (size_t)(k0 + row) * DIM + ch * 8);
        }
    };

    issue_kv(0, 0);
    CP_COMMIT();
    issue_kv(1, 1);      // nkt >= 2 always
    CP_COMMIT();

    float cs[8][4];
    float co[8][4];
#pragma unroll
    for (int j = 0; j < 8; j++)
#pragma unroll
        for (int t = 0; t < 4; t++) co[j][t] = 0.f;

    float m0v = -1e30f, m1v = -1e30f, l0v = 0.f, l1v = 0.f;

    const int r0 = lane >> 2;
    const int ccol = (lane & 3) * 2;
    const int gi0 = q0 + wid * 16 + r0;
    const int gi1 = gi0 + 8;

    for (int kt = 0; kt < nkt; kt++) {
        const int s = kt % 3;
        const int k0 = kt * 64;
        const uint32_t stgo = STG0 + s * 16384;

        if (kt + 1 < nkt) { CP_WAIT(1); } else { CP_WAIT(0); }
        __syncthreads();
        if (kt + 2 < nkt) { issue_kv(kt + 2, (kt + 2) % 3); CP_COMMIT(); }

        // Fully-masked warps (diagonal tile, query rows < tile keys) skip.
        if (kt == nkt - 1 && wid < 4) continue;

        // ---- S = Q K^T ----
#pragma unroll
        for (int j = 0; j < 8; j++)
#pragma unroll
            for (int t = 0; t < 4; t++) cs[j][t] = 0.f;

        uint32_t kHiB = sbase + stgo;
#pragma unroll
        for (int ks = 0; ks < 4; ks++) {
            uint32_t qoff = SWZ128((uint32_t)((wid * 16 + lr) * 128 + ks * 32 + lk * 16));
            uint32_t ahi[4];
            LDSM_X4(ahi[0], ahi[1], ahi[2], ahi[3], sbase + Q_HI + qoff);
#pragma unroll
            for (int ng = 0; ng < 4; ng++) {
                uint32_t boff = SWZ128((uint32_t)((ng * 16 + lr) * 128 + ks * 32 + lk * 16));
                uint32_t bh0, bh1, bh2, bh3;
                LDSM_X4(bh0, bh1, bh2, bh3, kHiB + boff);
                MMAF16(cs[ng*2+0], ahi, bh0, bh2);
                MMAF16(cs[ng*2+1], ahi, bh1, bh3);
            }
        }

        // ---- ALiBi + causal mask ----
#pragma unroll
        for (int nb = 0; nb < 8; nb++) {
#pragma unroll
            for (int cidx = 0; cidx < 2; cidx++) {
                int gj = k0 + nb * 8 + ccol + cidx;
                float rel0 = slope * (float)(gj - gi0);
                float rel1 = slope * (float)(gj - gi1);
                cs[nb][cidx]     = (gj > gi0) ? -1e30f : cs[nb][cidx]     - rel0;
                cs[nb][2 + cidx] = (gj > gi1) ? -1e30f : cs[nb][2 + cidx] - rel1;
            }
        }

        // ---- online softmax ----
        float mx0 = -1e30f, mx1 = -1e30f;
#pragma unroll
        for (int nb = 0; nb < 8; nb++) {
            mx0 = fmaxf(mx0, fmaxf(cs[nb][0], cs[nb][1]));
            mx1 = fmaxf(mx1, fmaxf(cs[nb][2], cs[nb][3]));
        }
        mx0 = fmaxf(mx0, __shfl_xor_sync(0xffffffff, mx0, 1));
        mx0 = fmaxf(mx0, __shfl_xor_sync(0xffffffff, mx0, 2));
        mx1 = fmaxf(mx1, __shfl_xor_sync(0xffffffff, mx1, 1));
        mx1 = fmaxf(mx1, __shfl_xor_sync(0xffffffff, mx1, 2));

        float mn0 = fmaxf(m0v, mx0), mn1 = fmaxf(m1v, mx1);
        float corr0 = __expf(m0v - mn0), corr1 = __expf(m1v - mn1);
        m0v = mn0; m1v = mn1;

        float sum0 = 0.f, sum1 = 0.f;
        const int prow0 = wid * 16 + r0;
#pragma unroll
        for (int nb = 0; nb < 8; nb++) {
            float p00 = __expf(cs[nb][0] - mn0);
            float p01 = __expf(cs[nb][1] - mn0);
            float p10 = __expf(cs[nb][2] - mn1);
            float p11 = __expf(cs[nb][3] - mn1);
            sum0 += p00 + p01;
            sum1 += p10 + p11;
            uint32_t off0 = SWZ128((uint32_t)(prow0 * 128 + nb * 16 + (lane & 3) * 4));
            uint32_t off1 = SWZ128((uint32_t)((prow0 + 8) * 128 + nb * 16 + (lane & 3) * 4));
            *(uint32_t*)(smem + P_HI + off0) = pack_h2(p00, p01);
            *(uint32_t*)(smem + P_HI + off1) = pack_h2(p10, p11);
        }
        sum0 += __shfl_xor_sync(0xffffffff, sum0, 1);
        sum0 += __shfl_xor_sync(0xffffffff, sum0, 2);
        sum1 += __shfl_xor_sync(0xffffffff, sum1, 1);
        sum1 += __shfl_xor_sync(0xffffffff, sum1, 2);
        l0v = l0v * corr0 + sum0;
        l1v = l1v * corr1 + sum1;

#pragma unroll
        for (int nb = 0; nb < 8; nb++) {
            co[nb][0] *= corr0; co[nb][1] *= corr0;
            co[nb][2] *= corr1; co[nb][3] *= corr1;
        }
        __syncwarp();

        // ---- O += P V (V via ldmatrix.trans) ----
        uint32_t vHiB = sbase + stgo + 8192;
#pragma unroll
        for (int ks = 0; ks < 4; ks++) {
            uint32_t poff = SWZ128((uint32_t)((wid * 16 + lr) * 128 + ks * 32 + lk * 16));
            uint32_t phi[4];
            LDSM_X4(phi[0], phi[1], phi[2], phi[3], sbase + P_HI + poff);
#pragma unroll
            for (int ng = 0; ng < 4; ng++) {
                uint32_t voff = SWZ128((uint32_t)((ks * 16 + lr) * 128 + ng * 32 + lk * 16));
                uint32_t vh0, vh1, vh2, vh3;
                LDSM_X4_T(vh0, vh1, vh2, vh3, vHiB + voff);
                MMAF16(co[ng*2+0], phi, vh0, vh1);
                MMAF16(co[ng*2+1], phi, vh2, vh3);
            }
        }
    }

    // ---- normalize + write fp16 hi ----
    float inv0 = 1.0f / l0v, inv1 = 1.0f / l1v;
    size_t row0 = (size_t)(b * SEQ + gi0) * DIM + h * HD;
    size_t row1 = (size_t)(b * SEQ + gi1) * DIM + h * HD;
#pragma unroll
    for (int nb = 0; nb < 8; nb++) {
        int d = nb * 8 + ccol;
        *(uint32_t*)(out_hi + row0 + d) = pack_h2(co[nb][0] * inv0, co[nb][1] * inv0);
        *(uint32_t*)(out_hi + row1 + d) = pack_h2(co[nb][2] * inv1, co[nb][3] * inv1);
    }
}

// ---------------------------------------------------------------------------
extern "C" void kernel_launch(void* const* d_in, const int* in_sizes, int n_in,
                              void* d_out, int out_size)
{
    const float* x    = (const float*)d_in[0];
    const float* Wqkv = (const float*)d_in[1];
    const float* Wo   = (const float*)d_in[2];
    float* out = (float*)d_out;

    __half *xhi, *wqh, *woh, *qhi, *khi, *vhi, *ahi;
    cudaGetSymbolAddress((void**)&xhi, g_xhi);
    cudaGetSymbolAddress((void**)&wqh, g_wqh);
    cudaGetSymbolAddress((void**)&woh, g_woh);
    cudaGetSymbolAddress((void**)&qhi, g_qhi);
    cudaGetSymbolAddress((void**)&khi, g_khi);
    cudaGetSymbolAddress((void**)&vhi, g_vhi);
    cudaGetSymbolAddress((void**)&ahi, g_ahi);

    cudaFuncSetAttribute(gemm_qkv, cudaFuncAttributeMaxDynamicSharedMemorySize, GEMM_SMEM);
    cudaFuncSetAttribute(gemm_out, cudaFuncAttributeMaxDynamicSharedMemorySize, GEMM_SMEM);
    cudaFuncSetAttribute(attn_mma, cudaFuncAttributeMaxDynamicSharedMemorySize, ATT_SMEM);

    // fused fp16 conversions (x + weights)
    {
        int n4 = N4_X + N4_WQ + N4_WO;
        split_all<<<(n4 + 255) / 256, 256>>>(x, xhi, Wqkv, wqh, Wo, woh);
    }

    // 1) qkv projection -> fp16 Q(hi, scaled), K(hi), V(hi)
    {
        dim3 grid(3 * DIM / BN, NTOK / BM);   // (24, 32)
        gemm_qkv<<<grid, 128, GEMM_SMEM>>>(xhi, wqh, qhi, khi, vhi);
    }

    // 2) tensor-core flash attention (fp16 in, fp16 hi out)
    {
        dim3 grid(SEQ / 128, BATCH * HEADS);   // (16, 32)
        attn_mma<<<grid, 256, ATT_SMEM>>>(qhi, khi, vhi, ahi);
    }

    // 3) out = attn_hi @ Wo^T (fp32 out)
    {
        dim3 grid(DIM / BN, NTOK / BM);        // (8, 32)
        gemm_out<<<grid, 128, GEMM_SMEM>>>(ahi, woh, out);
    }
}